// round 13
// baseline (speedup 1.0000x reference)
#include <cuda_runtime.h>
#include <cuda_bf16.h>
#include <cuda_fp16.h>
#include <cstdint>

// Problem constants
#define EMB   768
#define NH    12
#define HD    64
#define SEQ   8192
#define QKV3  2304          // 3*EMB
#define QSCALE2 0.1803368801111731f   // (1/sqrt(64)) * log2(e)

// ---------------------------------------------------------------------------
// cp.async helpers
// ---------------------------------------------------------------------------
__device__ __forceinline__ void cp_async16(uint32_t dst, const void* src) {
    asm volatile("cp.async.ca.shared.global [%0], [%1], 16;" :: "r"(dst), "l"(src));
}
__device__ __forceinline__ void cp_commit() { asm volatile("cp.async.commit_group;"); }
__device__ __forceinline__ void cp_wait0()  { asm volatile("cp.async.wait_group 0;"); }

// ---------------------------------------------------------------------------
// Tensor-core helpers (baseline PTX, OK on compute_103)
// ---------------------------------------------------------------------------
#define LDSM_X4(r, addr) \
    asm volatile("ldmatrix.sync.aligned.m8n8.x4.shared.b16 {%0,%1,%2,%3}, [%4];" \
        : "=r"((r)[0]), "=r"((r)[1]), "=r"((r)[2]), "=r"((r)[3]) : "r"(addr))

#define LDSM_X4_T(r, addr) \
    asm volatile("ldmatrix.sync.aligned.m8n8.x4.trans.shared.b16 {%0,%1,%2,%3}, [%4];" \
        : "=r"((r)[0]), "=r"((r)[1]), "=r"((r)[2]), "=r"((r)[3]) : "r"(addr))

__device__ __forceinline__ void mma16816(float* c, const uint32_t* a,
                                         uint32_t b0, uint32_t b1) {
    asm volatile(
        "mma.sync.aligned.m16n8k16.row.col.f32.bf16.bf16.f32 "
        "{%0,%1,%2,%3}, {%4,%5,%6,%7}, {%8,%9}, {%0,%1,%2,%3};"
        : "+f"(c[0]), "+f"(c[1]), "+f"(c[2]), "+f"(c[3])
        : "r"(a[0]), "r"(a[1]), "r"(a[2]), "r"(a[3]), "r"(b0), "r"(b1));
}
__device__ __forceinline__ void mma16816h(float* c, const uint32_t* a,
                                          uint32_t b0, uint32_t b1) {
    asm volatile(
        "mma.sync.aligned.m16n8k16.row.col.f32.f16.f16.f32 "
        "{%0,%1,%2,%3}, {%4,%5,%6,%7}, {%8,%9}, {%0,%1,%2,%3};"
        : "+f"(c[0]), "+f"(c[1]), "+f"(c[2]), "+f"(c[3])
        : "r"(a[0]), "r"(a[1]), "r"(a[2]), "r"(a[3]), "r"(b0), "r"(b1));
}

// pack two fp32 -> f16x2 register {a low, b high}
__device__ __forceinline__ uint32_t cvt2_f16(float a, float b) {
    uint32_t r;
    asm("cvt.rn.f16x2.f32 %0, %1, %2;" : "=r"(r) : "f"(b), "f"(a));
    return r;
}

// Fast 2^t for t <= 0 (FMA pipe only, no MUFU/CVT). |err| ~ 1e-8 rel.
__device__ __forceinline__ float fexp2(float t) {
    t = fmaxf(t, -126.0f);
    float z  = t + 12582912.0f;            // round-to-nearest via magic
    int   iz = __float_as_int(z);          // low bits carry round(t) (wrapped)
    float fi = z - 12582912.0f;
    float f  = t - fi;                     // f in [-0.5, 0.5]
    float p  = 1.53533619e-4f;
    p = fmaf(p, f, 1.33988744e-3f);
    p = fmaf(p, f, 9.61843737e-3f);
    p = fmaf(p, f, 5.55033247e-2f);
    p = fmaf(p, f, 2.40226479e-1f);
    p = fmaf(p, f, 6.93147203e-1f);
    p = fmaf(p, f, 1.0f);
    return __int_as_float(__float_as_int(p) + (iz << 23));
}

// ---------------------------------------------------------------------------
// Scratch (device globals — no runtime allocation allowed)
// ---------------------------------------------------------------------------
__device__ float g_qkv[SEQ * QKV3];    // [S][3E] : q +0, k +768, v +1536
__device__ float g_attn[SEQ * EMB];    // [S][E]

__device__ __align__(16) __nv_bfloat16 g_xh[SEQ * EMB];     // x split
__device__ __align__(16) __nv_bfloat16 g_xl[SEQ * EMB];
__device__ __align__(16) __nv_bfloat16 g_ah[SEQ * EMB];     // attn split
__device__ __align__(16) __nv_bfloat16 g_al[SEQ * EMB];
__device__ __align__(16) __nv_bfloat16 g_wqh[QKV3 * EMB];   // Wqkv^T split [N][K]
__device__ __align__(16) __nv_bfloat16 g_wql[QKV3 * EMB];
__device__ __align__(16) __nv_bfloat16 g_woh[EMB * EMB];    // Wout^T split [N][K]
__device__ __align__(16) __nv_bfloat16 g_wol[EMB * EMB];

__device__ __align__(16) __half g_kf[NH * SEQ * HD];        // K fp16 single
__device__ __align__(16) __half g_vh[NH * SEQ * HD];        // V fp16 split
__device__ __align__(16) __half g_vl[NH * SEQ * HD];

// ---------------------------------------------------------------------------
// Split fp32 -> (hi, lo) bf16, elementwise (4 elems/thread)
// ---------------------------------------------------------------------------
__global__ void split_kernel(const float* __restrict__ src,
                             __nv_bfloat16* __restrict__ hi,
                             __nv_bfloat16* __restrict__ lo, int n4)
{
    const int i = blockIdx.x * blockDim.x + threadIdx.x;
    if (i >= n4) return;
    float4 v = ((const float4*)src)[i];
    __nv_bfloat16 h0 = __float2bfloat16(v.x), h1 = __float2bfloat16(v.y);
    __nv_bfloat16 h2 = __float2bfloat16(v.z), h3 = __float2bfloat16(v.w);
    __nv_bfloat162* hp = (__nv_bfloat162*)hi;
    __nv_bfloat162* lp = (__nv_bfloat162*)lo;
    hp[2 * i]     = __nv_bfloat162(h0, h1);
    hp[2 * i + 1] = __nv_bfloat162(h2, h3);
    lp[2 * i]     = __nv_bfloat162(__float2bfloat16(v.x - __bfloat162float(h0)),
                                   __float2bfloat16(v.y - __bfloat162float(h1)));
    lp[2 * i + 1] = __nv_bfloat162(__float2bfloat16(v.z - __bfloat162float(h2)),
                                   __float2bfloat16(v.w - __bfloat162float(h3)));
}

// ---------------------------------------------------------------------------
// Transpose + split: W[K][N] fp32 -> T{h,l}[N][K] bf16
// ---------------------------------------------------------------------------
__global__ void wtsplit_kernel(const float* __restrict__ W,
                               __nv_bfloat16* __restrict__ Th,
                               __nv_bfloat16* __restrict__ Tl, int K, int N)
{
    __shared__ float t[32][33];
    const int k0 = blockIdx.x * 32;
    const int n0 = blockIdx.y * 32;
    const int tx = threadIdx.x, ty = threadIdx.y;
    #pragma unroll
    for (int i = 0; i < 32; i += 8)
        t[ty + i][tx] = W[(size_t)(k0 + ty + i) * N + n0 + tx];
    __syncthreads();
    #pragma unroll
    for (int i = 0; i < 32; i += 8) {
        const float v = t[tx][ty + i];
        const __nv_bfloat16 h = __float2bfloat16(v);
        const size_t o = (size_t)(n0 + ty + i) * K + k0 + tx;
        Th[o] = h;
        Tl[o] = __float2bfloat16(v - __bfloat162float(h));
    }
}

// ---------------------------------------------------------------------------
// K/V prep: K -> fp16 single; V -> fp16 hi/lo split. Layout [h][tok][64].
// ---------------------------------------------------------------------------
__global__ void kvsplit_kernel(const float* __restrict__ qkv,
                               __half* __restrict__ kf,
                               __half* __restrict__ vh,
                               __half* __restrict__ vl)
{
    const int t = blockIdx.x;
    const int i = threadIdx.x;               // 0..191
    const int h = (4 * i) >> 6, d = (4 * i) & 63;
    const size_t o = ((size_t)h * SEQ + t) * HD + d;

    float4 kv = *(const float4*)&qkv[(size_t)t * QKV3 + 768 + 4 * i];
    *(__half2*)&kf[o]     = __half2(__float2half(kv.x), __float2half(kv.y));
    *(__half2*)&kf[o + 2] = __half2(__float2half(kv.z), __float2half(kv.w));

    float4 vv = *(const float4*)&qkv[(size_t)t * QKV3 + 1536 + 4 * i];
    {
        __half h0 = __float2half(vv.x), h1 = __float2half(vv.y);
        __half h2 = __float2half(vv.z), h3 = __float2half(vv.w);
        *(__half2*)&vh[o]     = __half2(h0, h1);
        *(__half2*)&vh[o + 2] = __half2(h2, h3);
        *(__half2*)&vl[o]     = __half2(__float2half(vv.x - __half2float(h0)),
                                        __float2half(vv.y - __half2float(h1)));
        *(__half2*)&vl[o + 2] = __half2(__float2half(vv.z - __half2float(h2)),
                                        __float2half(vv.w - __half2float(h3)));
    }
}

// ---------------------------------------------------------------------------
// bf16-split tensor-core GEMM — 2 CTAs/SM, term-major mma order
// ---------------------------------------------------------------------------
#define GT_TILE  10240u   // 128 * 40 * 2 bytes
#define GT_STAGE 40960u   // 4 tiles (Ah,Al,Bh,Bl)

__global__ __launch_bounds__(256, 2)
void gemm_mma_kernel(const __nv_bfloat16* __restrict__ Ah,
                     const __nv_bfloat16* __restrict__ Al,
                     const __nv_bfloat16* __restrict__ Bh,
                     const __nv_bfloat16* __restrict__ Bl,
                     const float* __restrict__ bias,
                     float* __restrict__ C,
                     int M, int N, int K)
{
    extern __shared__ char gsm[];
    const uint32_t smB = (uint32_t)__cvta_generic_to_shared(gsm);

    const int tid  = threadIdx.x;
    const int warp = tid >> 5, lane = tid & 31;
    const int wm   = warp >> 2;
    const int wn   = warp & 3;
    const int m0   = blockIdx.y * 128;
    const int n0   = blockIdx.x * 128;

    float acc[4][4][4];
    #pragma unroll
    for (int a = 0; a < 4; a++)
        #pragma unroll
        for (int b = 0; b < 4; b++)
            #pragma unroll
            for (int c = 0; c < 4; c++) acc[a][b][c] = 0.0f;

    auto copyChunk = [&](int k0c, int buf) {
        const uint32_t sb = smB + (uint32_t)buf * GT_STAGE;
        #pragma unroll
        for (int t = 0; t < 4; t++) {
            const __nv_bfloat16* gp = (t == 0) ? Ah : (t == 1) ? Al : (t == 2) ? Bh : Bl;
            const int base = (t < 2) ? m0 : n0;
            #pragma unroll
            for (int s = 0; s < 2; s++) {
                const int cid = tid + 256 * s;
                const int row = cid >> 2, kc = cid & 3;
                cp_async16(sb + t * GT_TILE + (uint32_t)(row * 40 + kc * 8) * 2,
                           gp + (size_t)(base + row) * K + k0c + kc * 8);
            }
        }
        cp_commit();
    };

    const int T = K >> 5;
    copyChunk(0, 0);

    for (int it = 0; it < T; it++) {
        cp_wait0();
        __syncthreads();
        if (it + 1 < T) copyChunk((it + 1) << 5, (it + 1) & 1);

        const uint32_t stg = smB + (uint32_t)(it & 1) * GT_STAGE;
        const int arow = wm * 64 + (lane & 15);
        const int brow = wn * 32 + (lane & 15);
        const int chi  = (lane >> 4) * 8;

        #pragma unroll
        for (int ks = 0; ks < 2; ks++) {
            const int col = ks * 16 + chi;
            uint32_t b_h[2][4], b_l[2][4];
            #pragma unroll
            for (int nt = 0; nt < 2; nt++) {
                const uint32_t bd = stg + 2 * GT_TILE +
                                    (uint32_t)((brow + nt * 16) * 40 + col) * 2;
                LDSM_X4(b_h[nt], bd);
                LDSM_X4(b_l[nt], bd + GT_TILE);
            }
            #pragma unroll
            for (int mt = 0; mt < 4; mt++) {
                uint32_t a_h[4], a_l[4];
                const uint32_t ad = stg + (uint32_t)((arow + mt * 16) * 40 + col) * 2;
                LDSM_X4(a_h, ad);
                LDSM_X4(a_l, ad + GT_TILE);
                // term-major: each acc touched at distance 4
                #pragma unroll
                for (int j = 0; j < 4; j++)
                    mma16816(acc[mt][j], a_h, b_h[j >> 1][j & 1], b_h[j >> 1][(j & 1) + 2]);
                #pragma unroll
                for (int j = 0; j < 4; j++)
                    mma16816(acc[mt][j], a_h, b_l[j >> 1][j & 1], b_l[j >> 1][(j & 1) + 2]);
                #pragma unroll
                for (int j = 0; j < 4; j++)
                    mma16816(acc[mt][j], a_l, b_h[j >> 1][j & 1], b_h[j >> 1][(j & 1) + 2]);
            }
        }
    }

    #pragma unroll
    for (int mt = 0; mt < 4; mt++) {
        const int r0 = m0 + wm * 64 + mt * 16 + (lane >> 2);
        #pragma unroll
        for (int j = 0; j < 4; j++) {
            const int cn = n0 + wn * 32 + j * 8 + 2 * (lane & 3);
            const float bx = bias[cn], by = bias[cn + 1];
            *(float2*)&C[(size_t)r0 * N + cn] =
                make_float2(acc[mt][j][0] + bx, acc[mt][j][1] + by);
            *(float2*)&C[(size_t)(r0 + 8) * N + cn] =
                make_float2(acc[mt][j][2] + bx, acc[mt][j][3] + by);
        }
    }
}

// ---------------------------------------------------------------------------
// Tensor-core strided flash attention (fp16, 2-term QK and PV), 3 branches.
// Block = 128 q x 1 head x 1 branch, 256 threads, 2 CTAs/SM (55.3KB smem).
// QK: (Qh+Ql) x K ; PV: P x (Vh+Vl). exp via FMA-pipe fexp2 (no MUFU).
// ---------------------------------------------------------------------------
#define AP 72                       // smem pitch (fp16 elems)
#define A_QL   18432u               // Ql staging offset
#define A_V    18432u               // V ring base; K ring base = 0 (2 x 9216)
#define A_SMEM 55296u

__global__ __launch_bounds__(256, 2)
void attn_mma_kernel(const float* __restrict__ qkv,
                     const __half* __restrict__ kf,
                     const __half* __restrict__ vh,
                     const __half* __restrict__ vl,
                     float* __restrict__ attn_out)
{
    extern __shared__ char asm_[];
    const uint32_t smB = (uint32_t)__cvta_generic_to_shared(asm_);

    const int br = blockIdx.z;
    int L, dil;
    if (br == 0)      { L = 2048; dil = 1; }
    else if (br == 1) { L = 4096; dil = 2; }
    else              { L = 2048; dil = 4; }

    const int q0 = blockIdx.x * 128;
    if (q0 >= L) return;
    const int h    = blockIdx.y;
    const int tid  = threadIdx.x;
    const int warp = tid >> 5, lane = tid & 31;

    const size_t hoff = (size_t)h * SEQ * HD;

    auto copyKV = [&](int kt, int buf) {
        const int tok0 = kt * 64;
        const uint32_t kb   = smB + (uint32_t)buf * 9216u;
        const uint32_t vbuf = smB + A_V + (uint32_t)buf * 18432u;
        #pragma unroll
        for (int i = 0; i < 6; i++) {
            const int flat = tid + 256 * i;          // 0..1535
            const int sel  = flat >> 9;              // 0:K 1:Vh 2:Vl
            const int r    = (flat >> 3) & 63;
            const int c    = flat & 7;
            const size_t src = hoff + (size_t)(tok0 + r) * dil * HD + c * 8;
            const uint32_t doff = (uint32_t)(r * AP + c * 8) * 2;
            const __half* gp = (sel == 0) ? kf : (sel == 1) ? vh : vl;
            const uint32_t db = (sel == 0) ? kb : (sel == 1) ? vbuf : vbuf + 9216u;
            cp_async16(db + doff, gp + src);
        }
        cp_commit();
    };

    const int nkt = L >> 6;

    // Prologue: stage Q (scaled by QSCALE2, fp16 split) into smem (region
    // later recycled for the K/V rings), read fragments, then start copies.
    {
        const int qr = tid >> 1, qc0 = (tid & 1) * 32;
        const float* qsrc = qkv + (size_t)(q0 + qr) * dil * QKV3 + h * 64 + qc0;
        __half* Qh = (__half*)asm_;
        __half* Ql = Qh + 128 * AP;
        #pragma unroll
        for (int i = 0; i < 8; i++) {
            float4 v = *(const float4*)&qsrc[4 * i];
            v.x *= QSCALE2; v.y *= QSCALE2; v.z *= QSCALE2; v.w *= QSCALE2;
            __half h0 = __float2half(v.x), h1 = __float2half(v.y);
            __half h2 = __float2half(v.z), h3 = __float2half(v.w);
            const int o = qr * AP + qc0 + 4 * i;
            *(__half2*)&Qh[o]     = __half2(h0, h1);
            *(__half2*)&Qh[o + 2] = __half2(h2, h3);
            *(__half2*)&Ql[o]     = __half2(__float2half(v.x - __half2float(h0)),
                                            __float2half(v.y - __half2float(h1)));
            *(__half2*)&Ql[o + 2] = __half2(__float2half(v.z - __half2float(h2)),
                                            __float2half(v.w - __half2float(h3)));
        }
    }
    __syncthreads();

    uint32_t qfh[4][4], qfl[4][4];
    {
        const int qrow = 16 * warp + (lane & 15);
        #pragma unroll
        for (int ks = 0; ks < 4; ks++) {
            const uint32_t ad = smB + (uint32_t)(qrow * AP + ks * 16 + (lane >> 4) * 8) * 2;
            LDSM_X4(qfh[ks], ad);
            LDSM_X4(qfl[ks], ad + A_QL);
        }
    }
    __syncthreads();   // all warps done reading Q before K ring overwrites it

    copyKV(0, 0);

    float o[8][4];
    #pragma unroll
    for (int j = 0; j < 8; j++)
        #pragma unroll
        for (int c = 0; c < 4; c++) o[j][c] = 0.0f;
    float mrA = -1e30f, mrB = -1e30f, lrA = 0.0f, lrB = 0.0f;

    for (int kt = 0; kt < nkt; kt++) {
        cp_wait0();
        __syncthreads();
        if (kt + 1 < nkt) copyKV(kt + 1, (kt + 1) & 1);

        const int buf = kt & 1;
        const uint32_t kbase = smB + (uint32_t)buf * 9216u;
        const uint32_t vbase = smB + A_V + (uint32_t)buf * 18432u;

        // ---- S = Q K^T (2 terms: Qh*K, Ql*K), term-major ----
        float s[8][4];
        #pragma unroll
        for (int j = 0; j < 8; j++)
            #pragma unroll
            for (int c = 0; c < 4; c++) s[j][c] = 0.0f;

        #pragma unroll
        for (int ks = 0; ks < 4; ks++) {
            uint32_t kfr[4][4];
            #pragma unroll
            for (int g = 0; g < 4; g++) {
                const uint32_t ad = kbase +
                    (uint32_t)((g * 16 + (lane & 15)) * AP + ks * 16 + (lane >> 4) * 8) * 2;
                LDSM_X4(kfr[g], ad);
            }
            #pragma unroll
            for (int g = 0; g < 4; g++) {
                mma16816h(s[2 * g],     qfh[ks], kfr[g][0], kfr[g][2]);
                mma16816h(s[2 * g + 1], qfh[ks], kfr[g][1], kfr[g][3]);
            }
            #pragma unroll
            for (int g = 0; g < 4; g++) {
                mma16816h(s[2 * g],     qfl[ks], kfr[g][0], kfr[g][2]);
                mma16816h(s[2 * g + 1], qfl[ks], kfr[g][1], kfr[g][3]);
            }
        }

        // ---- online softmax in base-2 units; exp via FMA-pipe fexp2 ----
        float mA = -1e30f, mB = -1e30f;
        #pragma unroll
        for (int j = 0; j < 8; j++) {
            mA = fmaxf(mA, fmaxf(s[j][0], s[j][1]));
            mB = fmaxf(mB, fmaxf(s[j][2], s[j][3]));
        }
        mA = fmaxf(mA, __shfl_xor_sync(0xffffffffu, mA, 1));
        mA = fmaxf(mA, __shfl_xor_sync(0xffffffffu, mA, 2));
        mB = fmaxf(mB, __shfl_xor_sync(0xffffffffu, mB, 1));
        mB = fmaxf(mB, __shfl_xor_sync(0xffffffffu, mB, 2));

        const float mnA = fmaxf(mrA, mA), mnB = fmaxf(mrB, mB);
        const float alA = fexp2(mrA - mnA), alB = fexp2(mrB - mnB);
        mrA = mnA; mrB = mnB;

        float lsA = 0.0f, lsB = 0.0f;
        #pragma unroll
        for (int j = 0; j < 8; j++) {
            s[j][0] = fexp2(s[j][0] - mnA);
            s[j][1] = fexp2(s[j][1] - mnA);
            s[j][2] = fexp2(s[j][2] - mnB);
            s[j][3] = fexp2(s[j][3] - mnB);
            lsA += s[j][0] + s[j][1];
            lsB += s[j][2] + s[j][3];
        }
        lsA += __shfl_xor_sync(0xffffffffu, lsA, 1);
        lsA += __shfl_xor_sync(0xffffffffu, lsA, 2);
        lsB += __shfl_xor_sync(0xffffffffu, lsB, 1);
        lsB += __shfl_xor_sync(0xffffffffu, lsB, 2);
        lrA = lrA * alA + lsA;
        lrB = lrB * alB + lsB;

        #pragma unroll
        for (int j = 0; j < 8; j++) {
            o[j][0] *= alA; o[j][1] *= alA;
            o[j][2] *= alB; o[j][3] *= alB;
        }

        // ---- O += P V  (P single fp16 from regs; V split in smem) ----
        #pragma unroll
        for (int t = 0; t < 4; t++) {
            uint32_t pa[4];
            pa[0] = cvt2_f16(s[2 * t][0],     s[2 * t][1]);
            pa[1] = cvt2_f16(s[2 * t][2],     s[2 * t][3]);
            pa[2] = cvt2_f16(s[2 * t + 1][0], s[2 * t + 1][1]);
            pa[3] = cvt2_f16(s[2 * t + 1][2], s[2 * t + 1][3]);
            #pragma unroll
            for (int g = 0; g < 4; g++) {
                uint32_t vfh4[4], vfl4[4];
                const uint32_t ad = vbase +
                    (uint32_t)((16 * t + ((lane >> 3) & 1) * 8 + (lane & 7)) * AP +
                               16 * g + (lane >> 4) * 8) * 2;
                LDSM_X4_T(vfh4, ad);
                LDSM_X4_T(vfl4, ad + 9216u);
                mma16816h(o[2 * g],     pa, vfh4[0], vfh4[1]);
                mma16816h(o[2 * g + 1], pa, vfh4[2], vfh4[3]);
                mma16816h(o[2 * g],     pa, vfl4[0], vfl4[1]);
                mma16816h(o[2 * g + 1], pa, vfl4[2], vfl4[3]);
            }
        }
    }

    // Epilogue: o/l * (1/3), scatter-add
    const float w3 = 1.0f / 3.0f;
    const float invA = w3 / lrA, invB = w3 / lrB;
    const int rA = q0 + 16 * warp + (lane >> 2);
    float* baseA = attn_out + (size_t)rA * dil * EMB + h * 64;
    float* baseB = attn_out + (size_t)(rA + 8) * dil * EMB + h * 64;
    #pragma unroll
    for (int j = 0; j < 8; j++) {
        const int c = 8 * j + 2 * (lane & 3);
        atomicAdd(baseA + c,     o[j][0] * invA);
        atomicAdd(baseA + c + 1, o[j][1] * invA);
        atomicAdd(baseB + c,     o[j][2] * invB);
        atomicAdd(baseB + c + 1, o[j][3] * invB);
    }
}

// ---------------------------------------------------------------------------
// Launch
// ---------------------------------------------------------------------------
extern "C" void kernel_launch(void* const* d_in, const int* in_sizes, int n_in,
                              void* d_out, int out_size)
{
    const float* x    = (const float*)d_in[0];
    const float* Wqkv = (const float*)d_in[1];
    const float* bqkv = (const float*)d_in[2];
    const float* Wout = (const float*)d_in[3];
    const float* bout = (const float*)d_in[4];
    float*       out  = (float*)d_out;

    float *qkvp, *attnp;
    __nv_bfloat16 *xh, *xl, *ah, *al, *wqh, *wql, *woh, *wol;
    __half *kfp, *vhp, *vlp;
    cudaGetSymbolAddress((void**)&qkvp,  g_qkv);
    cudaGetSymbolAddress((void**)&attnp, g_attn);
    cudaGetSymbolAddress((void**)&xh,  g_xh);  cudaGetSymbolAddress((void**)&xl,  g_xl);
    cudaGetSymbolAddress((void**)&ah,  g_ah);  cudaGetSymbolAddress((void**)&al,  g_al);
    cudaGetSymbolAddress((void**)&wqh, g_wqh); cudaGetSymbolAddress((void**)&wql, g_wql);
    cudaGetSymbolAddress((void**)&woh, g_woh); cudaGetSymbolAddress((void**)&wol, g_wol);
    cudaGetSymbolAddress((void**)&kfp, g_kf);
    cudaGetSymbolAddress((void**)&vhp, g_vh);  cudaGetSymbolAddress((void**)&vlp, g_vl);

    const int GEMM_SMEM = 2 * GT_STAGE;   // 81920
    (void)cudaFuncSetAttribute((const void*)gemm_mma_kernel,
                               cudaFuncAttributeMaxDynamicSharedMemorySize, GEMM_SMEM);
    (void)cudaFuncSetAttribute((const void*)attn_mma_kernel,
                               cudaFuncAttributeMaxDynamicSharedMemorySize, A_SMEM);

    // 1) Split inputs to bf16 hi/lo
    split_kernel<<<(SEQ * EMB / 4 + 255) / 256, 256>>>(x, xh, xl, SEQ * EMB / 4);
    wtsplit_kernel<<<dim3(EMB / 32, QKV3 / 32), dim3(32, 8)>>>(Wqkv, wqh, wql, EMB, QKV3);
    wtsplit_kernel<<<dim3(EMB / 32, EMB / 32),  dim3(32, 8)>>>(Wout, woh, wol, EMB, EMB);

    // 2) QKV GEMM (tensor cores, bf16 split)
    {
        dim3 grid(QKV3 / 128, SEQ / 128);
        gemm_mma_kernel<<<grid, 256, GEMM_SMEM>>>(xh, xl, wqh, wql, bqkv, qkvp,
                                                  SEQ, QKV3, EMB);
    }

    // 3) K/V prep to fp16 (K single, V split)
    kvsplit_kernel<<<SEQ, 192>>>(qkvp, kfp, vhp, vlp);

    // 4) Zero attention accumulator
    cudaMemsetAsync(attnp, 0, (size_t)SEQ * EMB * sizeof(float));

    // 5) Attention (tensor cores, all 3 branches)
    {
        dim3 grid(32, NH, 3);
        attn_mma_kernel<<<grid, 256, A_SMEM>>>(qkvp, kfp, vhp, vlp, attnp);
    }

    // 6) Split attention output, then output projection (tensor cores)
    split_kernel<<<(SEQ * EMB / 4 + 255) / 256, 256>>>(attnp, ah, al, SEQ * EMB / 4);
    {
        dim3 grid(EMB / 128, SEQ / 128);
        gemm_mma_kernel<<<grid, 256, GEMM_SMEM>>>(ah, al, woh, wol, bout, out,
                                                  SEQ, EMB, EMB);
    }
}

// round 15
// speedup vs baseline: 1.7363x; 1.7363x over previous
#include <cuda_runtime.h>
#include <cuda_bf16.h>
#include <cuda_fp16.h>
#include <cstdint>

// Problem constants
#define EMB   768
#define NH    12
#define HD    64
#define SEQ   8192
#define QKV3  2304          // 3*EMB
#define QSCALE2 0.1803368801111731f   // (1/sqrt(64)) * log2(e)

// ---------------------------------------------------------------------------
// cp.async helpers
// ---------------------------------------------------------------------------
__device__ __forceinline__ void cp_async16(uint32_t dst, const void* src) {
    asm volatile("cp.async.ca.shared.global [%0], [%1], 16;" :: "r"(dst), "l"(src));
}
__device__ __forceinline__ void cp_commit() { asm volatile("cp.async.commit_group;"); }
__device__ __forceinline__ void cp_wait0()  { asm volatile("cp.async.wait_group 0;"); }

// ---------------------------------------------------------------------------
// Tensor-core helpers (baseline PTX, OK on compute_103)
// ---------------------------------------------------------------------------
#define LDSM_X4(r, addr) \
    asm volatile("ldmatrix.sync.aligned.m8n8.x4.shared.b16 {%0,%1,%2,%3}, [%4];" \
        : "=r"((r)[0]), "=r"((r)[1]), "=r"((r)[2]), "=r"((r)[3]) : "r"(addr))

#define LDSM_X4_T(r, addr) \
    asm volatile("ldmatrix.sync.aligned.m8n8.x4.trans.shared.b16 {%0,%1,%2,%3}, [%4];" \
        : "=r"((r)[0]), "=r"((r)[1]), "=r"((r)[2]), "=r"((r)[3]) : "r"(addr))

__device__ __forceinline__ void mma16816(float* c, const uint32_t* a,
                                         uint32_t b0, uint32_t b1) {
    asm volatile(
        "mma.sync.aligned.m16n8k16.row.col.f32.bf16.bf16.f32 "
        "{%0,%1,%2,%3}, {%4,%5,%6,%7}, {%8,%9}, {%0,%1,%2,%3};"
        : "+f"(c[0]), "+f"(c[1]), "+f"(c[2]), "+f"(c[3])
        : "r"(a[0]), "r"(a[1]), "r"(a[2]), "r"(a[3]), "r"(b0), "r"(b1));
}
__device__ __forceinline__ void mma16816h(float* c, const uint32_t* a,
                                          uint32_t b0, uint32_t b1) {
    asm volatile(
        "mma.sync.aligned.m16n8k16.row.col.f32.f16.f16.f32 "
        "{%0,%1,%2,%3}, {%4,%5,%6,%7}, {%8,%9}, {%0,%1,%2,%3};"
        : "+f"(c[0]), "+f"(c[1]), "+f"(c[2]), "+f"(c[3])
        : "r"(a[0]), "r"(a[1]), "r"(a[2]), "r"(a[3]), "r"(b0), "r"(b1));
}

// pack two fp32 -> f16x2 register {a low, b high}
__device__ __forceinline__ uint32_t cvt2_f16(float a, float b) {
    uint32_t r;
    asm("cvt.rn.f16x2.f32 %0, %1, %2;" : "=r"(r) : "f"(b), "f"(a));
    return r;
}

// Single-MUFU 2^x (log2(e) already folded into the scores via QSCALE2)
__device__ __forceinline__ float ex2(float x) {
    float r;
    asm("ex2.approx.f32 %0, %1;" : "=f"(r) : "f"(x));
    return r;
}

// ---------------------------------------------------------------------------
// Scratch (device globals — no runtime allocation allowed)
// ---------------------------------------------------------------------------
__device__ float g_qkv[SEQ * QKV3];    // [S][3E] : q +0, k +768, v +1536
__device__ float g_attn[SEQ * EMB];    // [S][E]

__device__ __align__(16) __nv_bfloat16 g_xh[SEQ * EMB];     // x split
__device__ __align__(16) __nv_bfloat16 g_xl[SEQ * EMB];
__device__ __align__(16) __nv_bfloat16 g_ah[SEQ * EMB];     // attn split
__device__ __align__(16) __nv_bfloat16 g_al[SEQ * EMB];
__device__ __align__(16) __nv_bfloat16 g_wqh[QKV3 * EMB];   // Wqkv^T split [N][K]
__device__ __align__(16) __nv_bfloat16 g_wql[QKV3 * EMB];
__device__ __align__(16) __nv_bfloat16 g_woh[EMB * EMB];    // Wout^T split [N][K]
__device__ __align__(16) __nv_bfloat16 g_wol[EMB * EMB];

__device__ __align__(16) __half g_kf[NH * SEQ * HD];        // K fp16 single
__device__ __align__(16) __half g_vh[NH * SEQ * HD];        // V fp16 split
__device__ __align__(16) __half g_vl[NH * SEQ * HD];

// ---------------------------------------------------------------------------
// Split fp32 -> (hi, lo) bf16, elementwise (4 elems/thread)
// ---------------------------------------------------------------------------
__global__ void split_kernel(const float* __restrict__ src,
                             __nv_bfloat16* __restrict__ hi,
                             __nv_bfloat16* __restrict__ lo, int n4)
{
    const int i = blockIdx.x * blockDim.x + threadIdx.x;
    if (i >= n4) return;
    float4 v = ((const float4*)src)[i];
    __nv_bfloat16 h0 = __float2bfloat16(v.x), h1 = __float2bfloat16(v.y);
    __nv_bfloat16 h2 = __float2bfloat16(v.z), h3 = __float2bfloat16(v.w);
    __nv_bfloat162* hp = (__nv_bfloat162*)hi;
    __nv_bfloat162* lp = (__nv_bfloat162*)lo;
    hp[2 * i]     = __nv_bfloat162(h0, h1);
    hp[2 * i + 1] = __nv_bfloat162(h2, h3);
    lp[2 * i]     = __nv_bfloat162(__float2bfloat16(v.x - __bfloat162float(h0)),
                                   __float2bfloat16(v.y - __bfloat162float(h1)));
    lp[2 * i + 1] = __nv_bfloat162(__float2bfloat16(v.z - __bfloat162float(h2)),
                                   __float2bfloat16(v.w - __bfloat162float(h3)));
}

// ---------------------------------------------------------------------------
// Transpose + split: W[K][N] fp32 -> T{h,l}[N][K] bf16
// ---------------------------------------------------------------------------
__global__ void wtsplit_kernel(const float* __restrict__ W,
                               __nv_bfloat16* __restrict__ Th,
                               __nv_bfloat16* __restrict__ Tl, int K, int N)
{
    __shared__ float t[32][33];
    const int k0 = blockIdx.x * 32;
    const int n0 = blockIdx.y * 32;
    const int tx = threadIdx.x, ty = threadIdx.y;
    #pragma unroll
    for (int i = 0; i < 32; i += 8)
        t[ty + i][tx] = W[(size_t)(k0 + ty + i) * N + n0 + tx];
    __syncthreads();
    #pragma unroll
    for (int i = 0; i < 32; i += 8) {
        const float v = t[tx][ty + i];
        const __nv_bfloat16 h = __float2bfloat16(v);
        const size_t o = (size_t)(n0 + ty + i) * K + k0 + tx;
        Th[o] = h;
        Tl[o] = __float2bfloat16(v - __bfloat162float(h));
    }
}

// ---------------------------------------------------------------------------
// K/V prep: K -> fp16 single; V -> fp16 hi/lo split. Layout [h][tok][64].
// ---------------------------------------------------------------------------
__global__ void kvsplit_kernel(const float* __restrict__ qkv,
                               __half* __restrict__ kf,
                               __half* __restrict__ vh,
                               __half* __restrict__ vl)
{
    const int t = blockIdx.x;
    const int i = threadIdx.x;               // 0..191
    const int h = (4 * i) >> 6, d = (4 * i) & 63;
    const size_t o = ((size_t)h * SEQ + t) * HD + d;

    float4 kv = *(const float4*)&qkv[(size_t)t * QKV3 + 768 + 4 * i];
    *(__half2*)&kf[o]     = __half2(__float2half(kv.x), __float2half(kv.y));
    *(__half2*)&kf[o + 2] = __half2(__float2half(kv.z), __float2half(kv.w));

    float4 vv = *(const float4*)&qkv[(size_t)t * QKV3 + 1536 + 4 * i];
    {
        __half h0 = __float2half(vv.x), h1 = __float2half(vv.y);
        __half h2 = __float2half(vv.z), h3 = __float2half(vv.w);
        *(__half2*)&vh[o]     = __half2(h0, h1);
        *(__half2*)&vh[o + 2] = __half2(h2, h3);
        *(__half2*)&vl[o]     = __half2(__float2half(vv.x - __half2float(h0)),
                                        __float2half(vv.y - __half2float(h1)));
        *(__half2*)&vl[o + 2] = __half2(__float2half(vv.z - __half2float(h2)),
                                        __float2half(vv.w - __half2float(h3)));
    }
}

// ---------------------------------------------------------------------------
// bf16-split tensor-core GEMM — 2 CTAs/SM; inner loop is the R11 (264us)
// ordering, reverted verbatim after R12's reorder regressed it to 410us.
// ---------------------------------------------------------------------------
#define GT_TILE  10240u   // 128 * 40 * 2 bytes
#define GT_STAGE 40960u   // 4 tiles (Ah,Al,Bh,Bl)

__global__ __launch_bounds__(256, 2)
void gemm_mma_kernel(const __nv_bfloat16* __restrict__ Ah,
                     const __nv_bfloat16* __restrict__ Al,
                     const __nv_bfloat16* __restrict__ Bh,
                     const __nv_bfloat16* __restrict__ Bl,
                     const float* __restrict__ bias,
                     float* __restrict__ C,
                     int M, int N, int K)
{
    extern __shared__ char gsm[];
    const uint32_t smB = (uint32_t)__cvta_generic_to_shared(gsm);

    const int tid  = threadIdx.x;
    const int warp = tid >> 5, lane = tid & 31;
    const int wm   = warp >> 2;
    const int wn   = warp & 3;
    const int m0   = blockIdx.y * 128;
    const int n0   = blockIdx.x * 128;

    float acc[4][4][4];
    #pragma unroll
    for (int a = 0; a < 4; a++)
        #pragma unroll
        for (int b = 0; b < 4; b++)
            #pragma unroll
            for (int c = 0; c < 4; c++) acc[a][b][c] = 0.0f;

    auto copyChunk = [&](int k0c, int buf) {
        const uint32_t sb = smB + (uint32_t)buf * GT_STAGE;
        #pragma unroll
        for (int t = 0; t < 4; t++) {
            const __nv_bfloat16* gp = (t == 0) ? Ah : (t == 1) ? Al : (t == 2) ? Bh : Bl;
            const int base = (t < 2) ? m0 : n0;
            #pragma unroll
            for (int s = 0; s < 2; s++) {
                const int cid = tid + 256 * s;
                const int row = cid >> 2, kc = cid & 3;
                cp_async16(sb + t * GT_TILE + (uint32_t)(row * 40 + kc * 8) * 2,
                           gp + (size_t)(base + row) * K + k0c + kc * 8);
            }
        }
        cp_commit();
    };

    const int T = K >> 5;
    copyChunk(0, 0);

    for (int it = 0; it < T; it++) {
        cp_wait0();
        __syncthreads();
        if (it + 1 < T) copyChunk((it + 1) << 5, (it + 1) & 1);

        const uint32_t stg = smB + (uint32_t)(it & 1) * GT_STAGE;
        const int arow = wm * 64 + (lane & 15);
        const int brow = wn * 32 + (lane & 15);
        const int chi  = (lane >> 4) * 8;

        #pragma unroll
        for (int ks = 0; ks < 2; ks++) {
            const int col = ks * 16 + chi;
            uint32_t b_h[2][4], b_l[2][4];
            #pragma unroll
            for (int nt = 0; nt < 2; nt++) {
                const uint32_t bd = stg + 2 * GT_TILE +
                                    (uint32_t)((brow + nt * 16) * 40 + col) * 2;
                LDSM_X4(b_h[nt], bd);
                LDSM_X4(b_l[nt], bd + GT_TILE);
            }
            #pragma unroll
            for (int mt = 0; mt < 4; mt++) {
                uint32_t a_h[4], a_l[4];
                const uint32_t ad = stg + (uint32_t)((arow + mt * 16) * 40 + col) * 2;
                LDSM_X4(a_h, ad);
                LDSM_X4(a_l, ad + GT_TILE);
                #pragma unroll
                for (int j = 0; j < 4; j++) {
                    const int nt = j >> 1, hf = j & 1;
                    mma16816(acc[mt][j], a_h, b_h[nt][hf], b_h[nt][hf + 2]);
                    mma16816(acc[mt][j], a_h, b_l[nt][hf], b_l[nt][hf + 2]);
                    mma16816(acc[mt][j], a_l, b_h[nt][hf], b_h[nt][hf + 2]);
                }
            }
        }
    }

    #pragma unroll
    for (int mt = 0; mt < 4; mt++) {
        const int r0 = m0 + wm * 64 + mt * 16 + (lane >> 2);
        #pragma unroll
        for (int j = 0; j < 4; j++) {
            const int cn = n0 + wn * 32 + j * 8 + 2 * (lane & 3);
            const float bx = bias[cn], by = bias[cn + 1];
            *(float2*)&C[(size_t)r0 * N + cn] =
                make_float2(acc[mt][j][0] + bx, acc[mt][j][1] + by);
            *(float2*)&C[(size_t)(r0 + 8) * N + cn] =
                make_float2(acc[mt][j][2] + bx, acc[mt][j][3] + by);
        }
    }
}

// ---------------------------------------------------------------------------
// Tensor-core strided flash attention (fp16, 2-term QK and PV), 3 branches.
// Block = 128 q x 1 head x 1 branch, 256 threads, 2 CTAs/SM (55.3KB smem).
// exp via single MUFU ex2 (log2(e) folded into Q scale).
// ---------------------------------------------------------------------------
#define AP 72                       // smem pitch (fp16 elems)
#define A_QL   18432u               // Ql staging offset
#define A_V    18432u               // V ring base; K ring base = 0 (2 x 9216)
#define A_SMEM 55296u

__global__ __launch_bounds__(256, 2)
void attn_mma_kernel(const float* __restrict__ qkv,
                     const __half* __restrict__ kf,
                     const __half* __restrict__ vh,
                     const __half* __restrict__ vl,
                     float* __restrict__ attn_out)
{
    extern __shared__ char asm_[];
    const uint32_t smB = (uint32_t)__cvta_generic_to_shared(asm_);

    const int br = blockIdx.z;
    int L, dil;
    if (br == 0)      { L = 2048; dil = 1; }
    else if (br == 1) { L = 4096; dil = 2; }
    else              { L = 2048; dil = 4; }

    const int q0 = blockIdx.x * 128;
    if (q0 >= L) return;
    const int h    = blockIdx.y;
    const int tid  = threadIdx.x;
    const int warp = tid >> 5, lane = tid & 31;

    const size_t hoff = (size_t)h * SEQ * HD;

    auto copyKV = [&](int kt, int buf) {
        const int tok0 = kt * 64;
        const uint32_t kb   = smB + (uint32_t)buf * 9216u;
        const uint32_t vbuf = smB + A_V + (uint32_t)buf * 18432u;
        #pragma unroll
        for (int i = 0; i < 6; i++) {
            const int flat = tid + 256 * i;          // 0..1535
            const int sel  = flat >> 9;              // 0:K 1:Vh 2:Vl
            const int r    = (flat >> 3) & 63;
            const int c    = flat & 7;
            const size_t src = hoff + (size_t)(tok0 + r) * dil * HD + c * 8;
            const uint32_t doff = (uint32_t)(r * AP + c * 8) * 2;
            const __half* gp = (sel == 0) ? kf : (sel == 1) ? vh : vl;
            const uint32_t db = (sel == 0) ? kb : (sel == 1) ? vbuf : vbuf + 9216u;
            cp_async16(db + doff, gp + src);
        }
        cp_commit();
    };

    const int nkt = L >> 6;

    // Prologue: stage Q (scaled by QSCALE2, fp16 split) into smem (region
    // later recycled for the K/V rings), read fragments, then start copies.
    {
        const int qr = tid >> 1, qc0 = (tid & 1) * 32;
        const float* qsrc = qkv + (size_t)(q0 + qr) * dil * QKV3 + h * 64 + qc0;
        __half* Qh = (__half*)asm_;
        __half* Ql = Qh + 128 * AP;
        #pragma unroll
        for (int i = 0; i < 8; i++) {
            float4 v = *(const float4*)&qsrc[4 * i];
            v.x *= QSCALE2; v.y *= QSCALE2; v.z *= QSCALE2; v.w *= QSCALE2;
            __half h0 = __float2half(v.x), h1 = __float2half(v.y);
            __half h2 = __float2half(v.z), h3 = __float2half(v.w);
            const int o = qr * AP + qc0 + 4 * i;
            *(__half2*)&Qh[o]     = __half2(h0, h1);
            *(__half2*)&Qh[o + 2] = __half2(h2, h3);
            *(__half2*)&Ql[o]     = __half2(__float2half(v.x - __half2float(h0)),
                                            __float2half(v.y - __half2float(h1)));
            *(__half2*)&Ql[o + 2] = __half2(__float2half(v.z - __half2float(h2)),
                                            __float2half(v.w - __half2float(h3)));
        }
    }
    __syncthreads();

    uint32_t qfh[4][4], qfl[4][4];
    {
        const int qrow = 16 * warp + (lane & 15);
        #pragma unroll
        for (int ks = 0; ks < 4; ks++) {
            const uint32_t ad = smB + (uint32_t)(qrow * AP + ks * 16 + (lane >> 4) * 8) * 2;
            LDSM_X4(qfh[ks], ad);
            LDSM_X4(qfl[ks], ad + A_QL);
        }
    }
    __syncthreads();   // all warps done reading Q before K ring overwrites it

    copyKV(0, 0);

    float o[8][4];
    #pragma unroll
    for (int j = 0; j < 8; j++)
        #pragma unroll
        for (int c = 0; c < 4; c++) o[j][c] = 0.0f;
    float mrA = -1e30f, mrB = -1e30f, lrA = 0.0f, lrB = 0.0f;

    for (int kt = 0; kt < nkt; kt++) {
        cp_wait0();
        __syncthreads();
        if (kt + 1 < nkt) copyKV(kt + 1, (kt + 1) & 1);

        const int buf = kt & 1;
        const uint32_t kbase = smB + (uint32_t)buf * 9216u;
        const uint32_t vbase = smB + A_V + (uint32_t)buf * 18432u;

        // ---- S = Q K^T (2 terms: Qh*K, Ql*K) ----
        float s[8][4];
        #pragma unroll
        for (int j = 0; j < 8; j++)
            #pragma unroll
            for (int c = 0; c < 4; c++) s[j][c] = 0.0f;

        #pragma unroll
        for (int ks = 0; ks < 4; ks++) {
            uint32_t kfr[4][4];
            #pragma unroll
            for (int g = 0; g < 4; g++) {
                const uint32_t ad = kbase +
                    (uint32_t)((g * 16 + (lane & 15)) * AP + ks * 16 + (lane >> 4) * 8) * 2;
                LDSM_X4(kfr[g], ad);
            }
            #pragma unroll
            for (int g = 0; g < 4; g++) {
                mma16816h(s[2 * g],     qfh[ks], kfr[g][0], kfr[g][2]);
                mma16816h(s[2 * g + 1], qfh[ks], kfr[g][1], kfr[g][3]);
                mma16816h(s[2 * g],     qfl[ks], kfr[g][0], kfr[g][2]);
                mma16816h(s[2 * g + 1], qfl[ks], kfr[g][1], kfr[g][3]);
            }
        }

        // ---- online softmax in base-2 units; exp = single MUFU ex2 ----
        float mA = -1e30f, mB = -1e30f;
        #pragma unroll
        for (int j = 0; j < 8; j++) {
            mA = fmaxf(mA, fmaxf(s[j][0], s[j][1]));
            mB = fmaxf(mB, fmaxf(s[j][2], s[j][3]));
        }
        mA = fmaxf(mA, __shfl_xor_sync(0xffffffffu, mA, 1));
        mA = fmaxf(mA, __shfl_xor_sync(0xffffffffu, mA, 2));
        mB = fmaxf(mB, __shfl_xor_sync(0xffffffffu, mB, 1));
        mB = fmaxf(mB, __shfl_xor_sync(0xffffffffu, mB, 2));

        const float mnA = fmaxf(mrA, mA), mnB = fmaxf(mrB, mB);
        const float alA = ex2(mrA - mnA), alB = ex2(mrB - mnB);
        mrA = mnA; mrB = mnB;

        float lsA = 0.0f, lsB = 0.0f;
        #pragma unroll
        for (int j = 0; j < 8; j++) {
            s[j][0] = ex2(s[j][0] - mnA);
            s[j][1] = ex2(s[j][1] - mnA);
            s[j][2] = ex2(s[j][2] - mnB);
            s[j][3] = ex2(s[j][3] - mnB);
            lsA += s[j][0] + s[j][1];
            lsB += s[j][2] + s[j][3];
        }
        lsA += __shfl_xor_sync(0xffffffffu, lsA, 1);
        lsA += __shfl_xor_sync(0xffffffffu, lsA, 2);
        lsB += __shfl_xor_sync(0xffffffffu, lsB, 1);
        lsB += __shfl_xor_sync(0xffffffffu, lsB, 2);
        lrA = lrA * alA + lsA;
        lrB = lrB * alB + lsB;

        #pragma unroll
        for (int j = 0; j < 8; j++) {
            o[j][0] *= alA; o[j][1] *= alA;
            o[j][2] *= alB; o[j][3] *= alB;
        }

        // ---- O += P V  (P single fp16 from regs; V split in smem) ----
        #pragma unroll
        for (int t = 0; t < 4; t++) {
            uint32_t pa[4];
            pa[0] = cvt2_f16(s[2 * t][0],     s[2 * t][1]);
            pa[1] = cvt2_f16(s[2 * t][2],     s[2 * t][3]);
            pa[2] = cvt2_f16(s[2 * t + 1][0], s[2 * t + 1][1]);
            pa[3] = cvt2_f16(s[2 * t + 1][2], s[2 * t + 1][3]);
            #pragma unroll
            for (int g = 0; g < 4; g++) {
                uint32_t vfh4[4], vfl4[4];
                const uint32_t ad = vbase +
                    (uint32_t)((16 * t + ((lane >> 3) & 1) * 8 + (lane & 7)) * AP +
                               16 * g + (lane >> 4) * 8) * 2;
                LDSM_X4_T(vfh4, ad);
                LDSM_X4_T(vfl4, ad + 9216u);
                mma16816h(o[2 * g],     pa, vfh4[0], vfh4[1]);
                mma16816h(o[2 * g + 1], pa, vfh4[2], vfh4[3]);
                mma16816h(o[2 * g],     pa, vfl4[0], vfl4[1]);
                mma16816h(o[2 * g + 1], pa, vfl4[2], vfl4[3]);
            }
        }
    }

    // Epilogue: o/l * (1/3), scatter-add
    const float w3 = 1.0f / 3.0f;
    const float invA = w3 / lrA, invB = w3 / lrB;
    const int rA = q0 + 16 * warp + (lane >> 2);
    float* baseA = attn_out + (size_t)rA * dil * EMB + h * 64;
    float* baseB = attn_out + (size_t)(rA + 8) * dil * EMB + h * 64;
    #pragma unroll
    for (int j = 0; j < 8; j++) {
        const int c = 8 * j + 2 * (lane & 3);
        atomicAdd(baseA + c,     o[j][0] * invA);
        atomicAdd(baseA + c + 1, o[j][1] * invA);
        atomicAdd(baseB + c,     o[j][2] * invB);
        atomicAdd(baseB + c + 1, o[j][3] * invB);
    }
}

// ---------------------------------------------------------------------------
// Launch
// ---------------------------------------------------------------------------
extern "C" void kernel_launch(void* const* d_in, const int* in_sizes, int n_in,
                              void* d_out, int out_size)
{
    const float* x    = (const float*)d_in[0];
    const float* Wqkv = (const float*)d_in[1];
    const float* bqkv = (const float*)d_in[2];
    const float* Wout = (const float*)d_in[3];
    const float* bout = (const float*)d_in[4];
    float*       out  = (float*)d_out;

    float *qkvp, *attnp;
    __nv_bfloat16 *xh, *xl, *ah, *al, *wqh, *wql, *woh, *wol;
    __half *kfp, *vhp, *vlp;
    cudaGetSymbolAddress((void**)&qkvp,  g_qkv);
    cudaGetSymbolAddress((void**)&attnp, g_attn);
    cudaGetSymbolAddress((void**)&xh,  g_xh);  cudaGetSymbolAddress((void**)&xl,  g_xl);
    cudaGetSymbolAddress((void**)&ah,  g_ah);  cudaGetSymbolAddress((void**)&al,  g_al);
    cudaGetSymbolAddress((void**)&wqh, g_wqh); cudaGetSymbolAddress((void**)&wql, g_wql);
    cudaGetSymbolAddress((void**)&woh, g_woh); cudaGetSymbolAddress((void**)&wol, g_wol);
    cudaGetSymbolAddress((void**)&kfp, g_kf);
    cudaGetSymbolAddress((void**)&vhp, g_vh);  cudaGetSymbolAddress((void**)&vlp, g_vl);

    const int GEMM_SMEM = 2 * GT_STAGE;   // 81920
    (void)cudaFuncSetAttribute((const void*)gemm_mma_kernel,
                               cudaFuncAttributeMaxDynamicSharedMemorySize, GEMM_SMEM);
    (void)cudaFuncSetAttribute((const void*)attn_mma_kernel,
                               cudaFuncAttributeMaxDynamicSharedMemorySize, A_SMEM);

    // 1) Split inputs to bf16 hi/lo
    split_kernel<<<(SEQ * EMB / 4 + 255) / 256, 256>>>(x, xh, xl, SEQ * EMB / 4);
    wtsplit_kernel<<<dim3(EMB / 32, QKV3 / 32), dim3(32, 8)>>>(Wqkv, wqh, wql, EMB, QKV3);
    wtsplit_kernel<<<dim3(EMB / 32, EMB / 32),  dim3(32, 8)>>>(Wout, woh, wol, EMB, EMB);

    // 2) QKV GEMM (tensor cores, bf16 split)
    {
        dim3 grid(QKV3 / 128, SEQ / 128);
        gemm_mma_kernel<<<grid, 256, GEMM_SMEM>>>(xh, xl, wqh, wql, bqkv, qkvp,
                                                  SEQ, QKV3, EMB);
    }

    // 3) K/V prep to fp16 (K single, V split)
    kvsplit_kernel<<<SEQ, 192>>>(qkvp, kfp, vhp, vlp);

    // 4) Zero attention accumulator
    cudaMemsetAsync(attnp, 0, (size_t)SEQ * EMB * sizeof(float));

    // 5) Attention (tensor cores, all 3 branches)
    {
        dim3 grid(32, NH, 3);
        attn_mma_kernel<<<grid, 256, A_SMEM>>>(qkvp, kfp, vhp, vlp, attnp);
    }

    // 6) Split attention output, then output projection (tensor cores)
    split_kernel<<<(SEQ * EMB / 4 + 255) / 256, 256>>>(attnp, ah, al, SEQ * EMB / 4);
    {
        dim3 grid(EMB / 128, SEQ / 128);
        gemm_mma_kernel<<<grid, 256, GEMM_SMEM>>>(ah, al, woh, wol, bout, out,
                                                  SEQ, EMB, EMB);
    }
}

// round 16
// speedup vs baseline: 2.0897x; 1.2036x over previous
#include <cuda_runtime.h>
#include <cuda_bf16.h>
#include <cuda_fp16.h>
#include <cstdint>

// Problem constants
#define EMB   768
#define NH    12
#define HD    64
#define SEQ   8192
#define QKV3  2304          // 3*EMB
#define QSCALE2 0.1803368801111731f   // (1/sqrt(64)) * log2(e)

// ---------------------------------------------------------------------------
// cp.async helpers
// ---------------------------------------------------------------------------
__device__ __forceinline__ void cp_async16(uint32_t dst, const void* src) {
    asm volatile("cp.async.ca.shared.global [%0], [%1], 16;" :: "r"(dst), "l"(src));
}
__device__ __forceinline__ void cp_commit() { asm volatile("cp.async.commit_group;"); }
__device__ __forceinline__ void cp_wait0()  { asm volatile("cp.async.wait_group 0;"); }

// ---------------------------------------------------------------------------
// Tensor-core helpers (baseline PTX, OK on compute_103)
// ---------------------------------------------------------------------------
#define LDSM_X4(r, addr) \
    asm volatile("ldmatrix.sync.aligned.m8n8.x4.shared.b16 {%0,%1,%2,%3}, [%4];" \
        : "=r"((r)[0]), "=r"((r)[1]), "=r"((r)[2]), "=r"((r)[3]) : "r"(addr))

#define LDSM_X4_T(r, addr) \
    asm volatile("ldmatrix.sync.aligned.m8n8.x4.trans.shared.b16 {%0,%1,%2,%3}, [%4];" \
        : "=r"((r)[0]), "=r"((r)[1]), "=r"((r)[2]), "=r"((r)[3]) : "r"(addr))

__device__ __forceinline__ void mma16816(float* c, const uint32_t* a,
                                         uint32_t b0, uint32_t b1) {
    asm volatile(
        "mma.sync.aligned.m16n8k16.row.col.f32.bf16.bf16.f32 "
        "{%0,%1,%2,%3}, {%4,%5,%6,%7}, {%8,%9}, {%0,%1,%2,%3};"
        : "+f"(c[0]), "+f"(c[1]), "+f"(c[2]), "+f"(c[3])
        : "r"(a[0]), "r"(a[1]), "r"(a[2]), "r"(a[3]), "r"(b0), "r"(b1));
}
__device__ __forceinline__ void mma16816h(float* c, const uint32_t* a,
                                          uint32_t b0, uint32_t b1) {
    asm volatile(
        "mma.sync.aligned.m16n8k16.row.col.f32.f16.f16.f32 "
        "{%0,%1,%2,%3}, {%4,%5,%6,%7}, {%8,%9}, {%0,%1,%2,%3};"
        : "+f"(c[0]), "+f"(c[1]), "+f"(c[2]), "+f"(c[3])
        : "r"(a[0]), "r"(a[1]), "r"(a[2]), "r"(a[3]), "r"(b0), "r"(b1));
}

// pack two fp32 -> f16x2 register {a low, b high}
__device__ __forceinline__ uint32_t cvt2_f16(float a, float b) {
    uint32_t r;
    asm("cvt.rn.f16x2.f32 %0, %1, %2;" : "=r"(r) : "f"(b), "f"(a));
    return r;
}

// Single-MUFU 2^x (log2(e) already folded into the scores via QSCALE2)
__device__ __forceinline__ float ex2(float x) {
    float r;
    asm("ex2.approx.f32 %0, %1;" : "=f"(r) : "f"(x));
    return r;
}

// ---------------------------------------------------------------------------
// Scratch (device globals — no runtime allocation allowed)
// ---------------------------------------------------------------------------
__device__ float g_qkv[SEQ * QKV3];    // [S][3E] : q +0, k +768, v +1536
__device__ float g_attn[SEQ * EMB];    // [S][E]

__device__ __align__(16) __nv_bfloat16 g_xh[SEQ * EMB];     // x split
__device__ __align__(16) __nv_bfloat16 g_xl[SEQ * EMB];
__device__ __align__(16) __nv_bfloat16 g_ah[SEQ * EMB];     // attn split
__device__ __align__(16) __nv_bfloat16 g_al[SEQ * EMB];
__device__ __align__(16) __nv_bfloat16 g_wqh[QKV3 * EMB];   // Wqkv^T split [N][K]
__device__ __align__(16) __nv_bfloat16 g_wql[QKV3 * EMB];
__device__ __align__(16) __nv_bfloat16 g_woh[EMB * EMB];    // Wout^T split [N][K]
__device__ __align__(16) __nv_bfloat16 g_wol[EMB * EMB];

__device__ __align__(16) __half g_kf[NH * SEQ * HD];        // K fp16 single, [h][tok][d]
__device__ __align__(16) __half g_vf[NH * SEQ * HD];        // V fp16 single, [h][tok][d]

// ---------------------------------------------------------------------------
// Split fp32 -> (hi, lo) bf16, elementwise (4 elems/thread)
// ---------------------------------------------------------------------------
__global__ void split_kernel(const float* __restrict__ src,
                             __nv_bfloat16* __restrict__ hi,
                             __nv_bfloat16* __restrict__ lo, int n4)
{
    const int i = blockIdx.x * blockDim.x + threadIdx.x;
    if (i >= n4) return;
    float4 v = ((const float4*)src)[i];
    __nv_bfloat16 h0 = __float2bfloat16(v.x), h1 = __float2bfloat16(v.y);
    __nv_bfloat16 h2 = __float2bfloat16(v.z), h3 = __float2bfloat16(v.w);
    __nv_bfloat162* hp = (__nv_bfloat162*)hi;
    __nv_bfloat162* lp = (__nv_bfloat162*)lo;
    hp[2 * i]     = __nv_bfloat162(h0, h1);
    hp[2 * i + 1] = __nv_bfloat162(h2, h3);
    lp[2 * i]     = __nv_bfloat162(__float2bfloat16(v.x - __bfloat162float(h0)),
                                   __float2bfloat16(v.y - __bfloat162float(h1)));
    lp[2 * i + 1] = __nv_bfloat162(__float2bfloat16(v.z - __bfloat162float(h2)),
                                   __float2bfloat16(v.w - __bfloat162float(h3)));
}

// ---------------------------------------------------------------------------
// Transpose + split: W[K][N] fp32 -> T{h,l}[N][K] bf16
// ---------------------------------------------------------------------------
__global__ void wtsplit_kernel(const float* __restrict__ W,
                               __nv_bfloat16* __restrict__ Th,
                               __nv_bfloat16* __restrict__ Tl, int K, int N)
{
    __shared__ float t[32][33];
    const int k0 = blockIdx.x * 32;
    const int n0 = blockIdx.y * 32;
    const int tx = threadIdx.x, ty = threadIdx.y;
    #pragma unroll
    for (int i = 0; i < 32; i += 8)
        t[ty + i][tx] = W[(size_t)(k0 + ty + i) * N + n0 + tx];
    __syncthreads();
    #pragma unroll
    for (int i = 0; i < 32; i += 8) {
        const float v = t[tx][ty + i];
        const __nv_bfloat16 h = __float2bfloat16(v);
        const size_t o = (size_t)(n0 + ty + i) * K + k0 + tx;
        Th[o] = h;
        Tl[o] = __float2bfloat16(v - __bfloat162float(h));
    }
}

// ---------------------------------------------------------------------------
// K/V prep: K, V -> single fp16, per-head layout [h][tok][64].
// ---------------------------------------------------------------------------
__global__ void kvprep_kernel(const float* __restrict__ qkv,
                              __half* __restrict__ kf,
                              __half* __restrict__ vf)
{
    const int t = blockIdx.x;
    const int i = threadIdx.x;               // 0..191
    const int h = (4 * i) >> 6, d = (4 * i) & 63;
    const size_t o = ((size_t)h * SEQ + t) * HD + d;

    float4 kv = *(const float4*)&qkv[(size_t)t * QKV3 + 768 + 4 * i];
    *(__half2*)&kf[o]     = __half2(__float2half(kv.x), __float2half(kv.y));
    *(__half2*)&kf[o + 2] = __half2(__float2half(kv.z), __float2half(kv.w));

    float4 vv = *(const float4*)&qkv[(size_t)t * QKV3 + 1536 + 4 * i];
    *(__half2*)&vf[o]     = __half2(__float2half(vv.x), __float2half(vv.y));
    *(__half2*)&vf[o + 2] = __half2(__float2half(vv.z), __float2half(vv.w));
}

// ---------------------------------------------------------------------------
// bf16-split tensor-core GEMM — unchanged (proven 264-266us config)
// ---------------------------------------------------------------------------
#define GT_TILE  10240u   // 128 * 40 * 2 bytes
#define GT_STAGE 40960u   // 4 tiles (Ah,Al,Bh,Bl)

__global__ __launch_bounds__(256, 2)
void gemm_mma_kernel(const __nv_bfloat16* __restrict__ Ah,
                     const __nv_bfloat16* __restrict__ Al,
                     const __nv_bfloat16* __restrict__ Bh,
                     const __nv_bfloat16* __restrict__ Bl,
                     const float* __restrict__ bias,
                     float* __restrict__ C,
                     int M, int N, int K)
{
    extern __shared__ char gsm[];
    const uint32_t smB = (uint32_t)__cvta_generic_to_shared(gsm);

    const int tid  = threadIdx.x;
    const int warp = tid >> 5, lane = tid & 31;
    const int wm   = warp >> 2;
    const int wn   = warp & 3;
    const int m0   = blockIdx.y * 128;
    const int n0   = blockIdx.x * 128;

    float acc[4][4][4];
    #pragma unroll
    for (int a = 0; a < 4; a++)
        #pragma unroll
        for (int b = 0; b < 4; b++)
            #pragma unroll
            for (int c = 0; c < 4; c++) acc[a][b][c] = 0.0f;

    auto copyChunk = [&](int k0c, int buf) {
        const uint32_t sb = smB + (uint32_t)buf * GT_STAGE;
        #pragma unroll
        for (int t = 0; t < 4; t++) {
            const __nv_bfloat16* gp = (t == 0) ? Ah : (t == 1) ? Al : (t == 2) ? Bh : Bl;
            const int base = (t < 2) ? m0 : n0;
            #pragma unroll
            for (int s = 0; s < 2; s++) {
                const int cid = tid + 256 * s;
                const int row = cid >> 2, kc = cid & 3;
                cp_async16(sb + t * GT_TILE + (uint32_t)(row * 40 + kc * 8) * 2,
                           gp + (size_t)(base + row) * K + k0c + kc * 8);
            }
        }
        cp_commit();
    };

    const int T = K >> 5;
    copyChunk(0, 0);

    for (int it = 0; it < T; it++) {
        cp_wait0();
        __syncthreads();
        if (it + 1 < T) copyChunk((it + 1) << 5, (it + 1) & 1);

        const uint32_t stg = smB + (uint32_t)(it & 1) * GT_STAGE;
        const int arow = wm * 64 + (lane & 15);
        const int brow = wn * 32 + (lane & 15);
        const int chi  = (lane >> 4) * 8;

        #pragma unroll
        for (int ks = 0; ks < 2; ks++) {
            const int col = ks * 16 + chi;
            uint32_t b_h[2][4], b_l[2][4];
            #pragma unroll
            for (int nt = 0; nt < 2; nt++) {
                const uint32_t bd = stg + 2 * GT_TILE +
                                    (uint32_t)((brow + nt * 16) * 40 + col) * 2;
                LDSM_X4(b_h[nt], bd);
                LDSM_X4(b_l[nt], bd + GT_TILE);
            }
            #pragma unroll
            for (int mt = 0; mt < 4; mt++) {
                uint32_t a_h[4], a_l[4];
                const uint32_t ad = stg + (uint32_t)((arow + mt * 16) * 40 + col) * 2;
                LDSM_X4(a_h, ad);
                LDSM_X4(a_l, ad + GT_TILE);
                #pragma unroll
                for (int j = 0; j < 4; j++) {
                    const int nt = j >> 1, hf = j & 1;
                    mma16816(acc[mt][j], a_h, b_h[nt][hf], b_h[nt][hf + 2]);
                    mma16816(acc[mt][j], a_h, b_l[nt][hf], b_l[nt][hf + 2]);
                    mma16816(acc[mt][j], a_l, b_h[nt][hf], b_h[nt][hf + 2]);
                }
            }
        }
    }

    #pragma unroll
    for (int mt = 0; mt < 4; mt++) {
        const int r0 = m0 + wm * 64 + mt * 16 + (lane >> 2);
        #pragma unroll
        for (int j = 0; j < 4; j++) {
            const int cn = n0 + wn * 32 + j * 8 + 2 * (lane & 3);
            const float bx = bias[cn], by = bias[cn + 1];
            *(float2*)&C[(size_t)r0 * N + cn] =
                make_float2(acc[mt][j][0] + bx, acc[mt][j][1] + by);
            *(float2*)&C[(size_t)(r0 + 8) * N + cn] =
                make_float2(acc[mt][j][2] + bx, acc[mt][j][3] + by);
        }
    }
}

// ---------------------------------------------------------------------------
// Tensor-core strided flash attention, single-fp16 Q/K/P/V (64 mma/warp-tile).
// Block = 128 q x 1 head x 1 branch, 256 threads, 36.9KB smem, 2 CTAs/SM.
// Error budget: Q,K,P,V each ~1.0-1.4e-4 (rms-passthrough model) -> ~2.4e-4.
// ---------------------------------------------------------------------------
#define AP 72                       // smem pitch (fp16 elems)
#define A_V    18432u               // V ring base; K ring base = 0 (2 x 9216 each)
#define A_SMEM 36864u

__global__ __launch_bounds__(256, 2)
void attn_mma_kernel(const float* __restrict__ qkv,
                     const __half* __restrict__ kf,
                     const __half* __restrict__ vf,
                     float* __restrict__ attn_out)
{
    extern __shared__ char asm_[];
    const uint32_t smB = (uint32_t)__cvta_generic_to_shared(asm_);

    const int br = blockIdx.z;
    int L, dil;
    if (br == 0)      { L = 2048; dil = 1; }
    else if (br == 1) { L = 4096; dil = 2; }
    else              { L = 2048; dil = 4; }

    const int q0 = blockIdx.x * 128;
    if (q0 >= L) return;
    const int h    = blockIdx.y;
    const int tid  = threadIdx.x;
    const int warp = tid >> 5, lane = tid & 31;

    const size_t hoff = (size_t)h * SEQ * HD;

    auto copyKV = [&](int kt, int buf) {
        const int tok0 = kt * 64;
        const uint32_t kb = smB + (uint32_t)buf * 9216u;
        const uint32_t vb = smB + A_V + (uint32_t)buf * 9216u;
        #pragma unroll
        for (int i = 0; i < 4; i++) {
            const int flat = tid + 256 * i;          // 0..1023
            const int sel  = flat >> 9;              // 0:K 1:V
            const int r    = (flat >> 3) & 63;
            const int c    = flat & 7;
            const size_t src = hoff + (size_t)(tok0 + r) * dil * HD + c * 8;
            const uint32_t doff = (uint32_t)(r * AP + c * 8) * 2;
            cp_async16((sel ? vb : kb) + doff, (sel ? vf : kf) + src);
        }
        cp_commit();
    };

    const int nkt = L >> 6;

    // Prologue: stage Q (scaled, single fp16) into smem (region later
    // recycled for the K/V rings), read fragments, then start copies.
    {
        const int qr = tid >> 1, qc0 = (tid & 1) * 32;
        const float* qsrc = qkv + (size_t)(q0 + qr) * dil * QKV3 + h * 64 + qc0;
        __half* Qs = (__half*)asm_;
        #pragma unroll
        for (int i = 0; i < 8; i++) {
            float4 v = *(const float4*)&qsrc[4 * i];
            v.x *= QSCALE2; v.y *= QSCALE2; v.z *= QSCALE2; v.w *= QSCALE2;
            const int o = qr * AP + qc0 + 4 * i;
            *(__half2*)&Qs[o]     = __half2(__float2half(v.x), __float2half(v.y));
            *(__half2*)&Qs[o + 2] = __half2(__float2half(v.z), __float2half(v.w));
        }
    }
    __syncthreads();

    uint32_t qf[4][4];
    {
        const int qrow = 16 * warp + (lane & 15);
        #pragma unroll
        for (int ks = 0; ks < 4; ks++) {
            const uint32_t ad = smB + (uint32_t)(qrow * AP + ks * 16 + (lane >> 4) * 8) * 2;
            LDSM_X4(qf[ks], ad);
        }
    }
    __syncthreads();   // all warps done reading Q before K ring overwrites it

    copyKV(0, 0);

    float o[8][4];
    #pragma unroll
    for (int j = 0; j < 8; j++)
        #pragma unroll
        for (int c = 0; c < 4; c++) o[j][c] = 0.0f;
    float mrA = -1e30f, mrB = -1e30f, lrA = 0.0f, lrB = 0.0f;

    for (int kt = 0; kt < nkt; kt++) {
        cp_wait0();
        __syncthreads();
        if (kt + 1 < nkt) copyKV(kt + 1, (kt + 1) & 1);

        const int buf = kt & 1;
        const uint32_t kbase = smB + (uint32_t)buf * 9216u;
        const uint32_t vbase = smB + A_V + (uint32_t)buf * 9216u;

        // ---- S = Q K^T (single fp16) ----
        float s[8][4];
        #pragma unroll
        for (int j = 0; j < 8; j++)
            #pragma unroll
            for (int c = 0; c < 4; c++) s[j][c] = 0.0f;

        #pragma unroll
        for (int ks = 0; ks < 4; ks++) {
            uint32_t kfr[4][4];
            #pragma unroll
            for (int g = 0; g < 4; g++) {
                const uint32_t ad = kbase +
                    (uint32_t)((g * 16 + (lane & 15)) * AP + ks * 16 + (lane >> 4) * 8) * 2;
                LDSM_X4(kfr[g], ad);
            }
            #pragma unroll
            for (int g = 0; g < 4; g++) {
                mma16816h(s[2 * g],     qf[ks], kfr[g][0], kfr[g][2]);
                mma16816h(s[2 * g + 1], qf[ks], kfr[g][1], kfr[g][3]);
            }
        }

        // ---- online softmax in base-2 units; exp = single MUFU ex2 ----
        float mA = -1e30f, mB = -1e30f;
        #pragma unroll
        for (int j = 0; j < 8; j++) {
            mA = fmaxf(mA, fmaxf(s[j][0], s[j][1]));
            mB = fmaxf(mB, fmaxf(s[j][2], s[j][3]));
        }
        mA = fmaxf(mA, __shfl_xor_sync(0xffffffffu, mA, 1));
        mA = fmaxf(mA, __shfl_xor_sync(0xffffffffu, mA, 2));
        mB = fmaxf(mB, __shfl_xor_sync(0xffffffffu, mB, 1));
        mB = fmaxf(mB, __shfl_xor_sync(0xffffffffu, mB, 2));

        const float mnA = fmaxf(mrA, mA), mnB = fmaxf(mrB, mB);
        const float alA = ex2(mrA - mnA), alB = ex2(mrB - mnB);
        mrA = mnA; mrB = mnB;

        float lsA = 0.0f, lsB = 0.0f;
        #pragma unroll
        for (int j = 0; j < 8; j++) {
            s[j][0] = ex2(s[j][0] - mnA);
            s[j][1] = ex2(s[j][1] - mnA);
            s[j][2] = ex2(s[j][2] - mnB);
            s[j][3] = ex2(s[j][3] - mnB);
            lsA += s[j][0] + s[j][1];
            lsB += s[j][2] + s[j][3];
        }
        lsA += __shfl_xor_sync(0xffffffffu, lsA, 1);
        lsA += __shfl_xor_sync(0xffffffffu, lsA, 2);
        lsB += __shfl_xor_sync(0xffffffffu, lsB, 1);
        lsB += __shfl_xor_sync(0xffffffffu, lsB, 2);
        lrA = lrA * alA + lsA;
        lrB = lrB * alB + lsB;

        #pragma unroll
        for (int j = 0; j < 8; j++) {
            o[j][0] *= alA; o[j][1] *= alA;
            o[j][2] *= alB; o[j][3] *= alB;
        }

        // ---- O += P V  (P single fp16 from regs; V single in smem) ----
        #pragma unroll
        for (int t = 0; t < 4; t++) {
            uint32_t pa[4];
            pa[0] = cvt2_f16(s[2 * t][0],     s[2 * t][1]);
            pa[1] = cvt2_f16(s[2 * t][2],     s[2 * t][3]);
            pa[2] = cvt2_f16(s[2 * t + 1][0], s[2 * t + 1][1]);
            pa[3] = cvt2_f16(s[2 * t + 1][2], s[2 * t + 1][3]);
            #pragma unroll
            for (int g = 0; g < 4; g++) {
                uint32_t vf4[4];
                const uint32_t ad = vbase +
                    (uint32_t)((16 * t + ((lane >> 3) & 1) * 8 + (lane & 7)) * AP +
                               16 * g + (lane >> 4) * 8) * 2;
                LDSM_X4_T(vf4, ad);
                mma16816h(o[2 * g],     pa, vf4[0], vf4[1]);
                mma16816h(o[2 * g + 1], pa, vf4[2], vf4[3]);
            }
        }
    }

    // Epilogue: o/l * (1/3), scatter-add
    const float w3 = 1.0f / 3.0f;
    const float invA = w3 / lrA, invB = w3 / lrB;
    const int rA = q0 + 16 * warp + (lane >> 2);
    float* baseA = attn_out + (size_t)rA * dil * EMB + h * 64;
    float* baseB = attn_out + (size_t)(rA + 8) * dil * EMB + h * 64;
    #pragma unroll
    for (int j = 0; j < 8; j++) {
        const int c = 8 * j + 2 * (lane & 3);
        atomicAdd(baseA + c,     o[j][0] * invA);
        atomicAdd(baseA + c + 1, o[j][1] * invA);
        atomicAdd(baseB + c,     o[j][2] * invB);
        atomicAdd(baseB + c + 1, o[j][3] * invB);
    }
}

// ---------------------------------------------------------------------------
// Launch
// ---------------------------------------------------------------------------
extern "C" void kernel_launch(void* const* d_in, const int* in_sizes, int n_in,
                              void* d_out, int out_size)
{
    const float* x    = (const float*)d_in[0];
    const float* Wqkv = (const float*)d_in[1];
    const float* bqkv = (const float*)d_in[2];
    const float* Wout = (const float*)d_in[3];
    const float* bout = (const float*)d_in[4];
    float*       out  = (float*)d_out;

    float *qkvp, *attnp;
    __nv_bfloat16 *xh, *xl, *ah, *al, *wqh, *wql, *woh, *wol;
    __half *kfp, *vfp;
    cudaGetSymbolAddress((void**)&qkvp,  g_qkv);
    cudaGetSymbolAddress((void**)&attnp, g_attn);
    cudaGetSymbolAddress((void**)&xh,  g_xh);  cudaGetSymbolAddress((void**)&xl,  g_xl);
    cudaGetSymbolAddress((void**)&ah,  g_ah);  cudaGetSymbolAddress((void**)&al,  g_al);
    cudaGetSymbolAddress((void**)&wqh, g_wqh); cudaGetSymbolAddress((void**)&wql, g_wql);
    cudaGetSymbolAddress((void**)&woh, g_woh); cudaGetSymbolAddress((void**)&wol, g_wol);
    cudaGetSymbolAddress((void**)&kfp, g_kf);  cudaGetSymbolAddress((void**)&vfp, g_vf);

    const int GEMM_SMEM = 2 * GT_STAGE;   // 81920
    (void)cudaFuncSetAttribute((const void*)gemm_mma_kernel,
                               cudaFuncAttributeMaxDynamicSharedMemorySize, GEMM_SMEM);
    (void)cudaFuncSetAttribute((const void*)attn_mma_kernel,
                               cudaFuncAttributeMaxDynamicSharedMemorySize, A_SMEM);

    // 1) Split inputs to bf16 hi/lo
    split_kernel<<<(SEQ * EMB / 4 + 255) / 256, 256>>>(x, xh, xl, SEQ * EMB / 4);
    wtsplit_kernel<<<dim3(EMB / 32, QKV3 / 32), dim3(32, 8)>>>(Wqkv, wqh, wql, EMB, QKV3);
    wtsplit_kernel<<<dim3(EMB / 32, EMB / 32),  dim3(32, 8)>>>(Wout, woh, wol, EMB, EMB);

    // 2) QKV GEMM (tensor cores, bf16 split)
    {
        dim3 grid(QKV3 / 128, SEQ / 128);
        gemm_mma_kernel<<<grid, 256, GEMM_SMEM>>>(xh, xl, wqh, wql, bqkv, qkvp,
                                                  SEQ, QKV3, EMB);
    }

    // 3) K/V prep to fp16
    kvprep_kernel<<<SEQ, 192>>>(qkvp, kfp, vfp);

    // 4) Zero attention accumulator
    cudaMemsetAsync(attnp, 0, (size_t)SEQ * EMB * sizeof(float));

    // 5) Attention (tensor cores, all 3 branches)
    {
        dim3 grid(32, NH, 3);
        attn_mma_kernel<<<grid, 256, A_SMEM>>>(qkvp, kfp, vfp, attnp);
    }

    // 6) Split attention output, then output projection (tensor cores)
    split_kernel<<<(SEQ * EMB / 4 + 255) / 256, 256>>>(attnp, ah, al, SEQ * EMB / 4);
    {
        dim3 grid(EMB / 128, SEQ / 128);
        gemm_mma_kernel<<<grid, 256, GEMM_SMEM>>>(ah, al, woh, wol, bout, out,
                                                  SEQ, EMB, EMB);
    }
}

// round 17
// speedup vs baseline: 2.5086x; 1.2005x over previous
#include <cuda_runtime.h>
#include <cuda_bf16.h>
#include <cuda_fp16.h>
#include <cstdint>

// Problem constants
#define EMB   768
#define NH    12
#define HD    64
#define SEQ   8192
#define QKV3  2304          // 3*EMB
#define QSCALE2 0.1803368801111731f   // (1/sqrt(64)) * log2(e)

// ---------------------------------------------------------------------------
// cp.async helpers
// ---------------------------------------------------------------------------
__device__ __forceinline__ void cp_async16(uint32_t dst, const void* src) {
    asm volatile("cp.async.ca.shared.global [%0], [%1], 16;" :: "r"(dst), "l"(src));
}
__device__ __forceinline__ void cp_commit() { asm volatile("cp.async.commit_group;"); }
__device__ __forceinline__ void cp_wait0()  { asm volatile("cp.async.wait_group 0;"); }

// ---------------------------------------------------------------------------
// Tensor-core helpers (baseline PTX, OK on compute_103)
// ---------------------------------------------------------------------------
#define LDSM_X4(r, addr) \
    asm volatile("ldmatrix.sync.aligned.m8n8.x4.shared.b16 {%0,%1,%2,%3}, [%4];" \
        : "=r"((r)[0]), "=r"((r)[1]), "=r"((r)[2]), "=r"((r)[3]) : "r"(addr))

#define LDSM_X4_T(r, addr) \
    asm volatile("ldmatrix.sync.aligned.m8n8.x4.trans.shared.b16 {%0,%1,%2,%3}, [%4];" \
        : "=r"((r)[0]), "=r"((r)[1]), "=r"((r)[2]), "=r"((r)[3]) : "r"(addr))

__device__ __forceinline__ void mma16816h(float* c, const uint32_t* a,
                                          uint32_t b0, uint32_t b1) {
    asm volatile(
        "mma.sync.aligned.m16n8k16.row.col.f32.f16.f16.f32 "
        "{%0,%1,%2,%3}, {%4,%5,%6,%7}, {%8,%9}, {%0,%1,%2,%3};"
        : "+f"(c[0]), "+f"(c[1]), "+f"(c[2]), "+f"(c[3])
        : "r"(a[0]), "r"(a[1]), "r"(a[2]), "r"(a[3]), "r"(b0), "r"(b1));
}

// pack two fp32 -> f16x2 register {a low, b high}
__device__ __forceinline__ uint32_t cvt2_f16(float a, float b) {
    uint32_t r;
    asm("cvt.rn.f16x2.f32 %0, %1, %2;" : "=r"(r) : "f"(b), "f"(a));
    return r;
}

// Single-MUFU 2^x (log2(e) already folded into the scores via QSCALE2)
__device__ __forceinline__ float ex2(float x) {
    float r;
    asm("ex2.approx.f32 %0, %1;" : "=f"(r) : "f"(x));
    return r;
}

// ---------------------------------------------------------------------------
// Scratch (device globals — no runtime allocation allowed)
// ---------------------------------------------------------------------------
__device__ float g_qkv[SEQ * QKV3];    // [S][3E] : q +0, k +768, v +1536
__device__ float g_attn[SEQ * EMB];    // [S][E]

__device__ __align__(16) __half g_xh[SEQ * EMB];     // x split (fp16 hi/lo)
__device__ __align__(16) __half g_xl[SEQ * EMB];
__device__ __align__(16) __half g_ah[SEQ * EMB];     // attn split (fp16 hi/lo)
__device__ __align__(16) __half g_al[SEQ * EMB];
__device__ __align__(16) __half g_wq[QKV3 * EMB];    // Wqkv^T fp16 single [N][K]
__device__ __align__(16) __half g_wo[EMB * EMB];     // Wout^T fp16 single [N][K]

__device__ __align__(16) __half g_kf[NH * SEQ * HD]; // K fp16 single, [h][tok][d]
__device__ __align__(16) __half g_vf[NH * SEQ * HD]; // V fp16 single, [h][tok][d]

// ---------------------------------------------------------------------------
// Split fp32 -> (hi, lo) fp16, elementwise (4 elems/thread)
// ---------------------------------------------------------------------------
__global__ void splitf16_kernel(const float* __restrict__ src,
                                __half* __restrict__ hi,
                                __half* __restrict__ lo, int n4)
{
    const int i = blockIdx.x * blockDim.x + threadIdx.x;
    if (i >= n4) return;
    float4 v = ((const float4*)src)[i];
    __half h0 = __float2half(v.x), h1 = __float2half(v.y);
    __half h2 = __float2half(v.z), h3 = __float2half(v.w);
    __half2* hp = (__half2*)hi;
    __half2* lp = (__half2*)lo;
    hp[2 * i]     = __half2(h0, h1);
    hp[2 * i + 1] = __half2(h2, h3);
    lp[2 * i]     = __half2(__float2half(v.x - __half2float(h0)),
                            __float2half(v.y - __half2float(h1)));
    lp[2 * i + 1] = __half2(__float2half(v.z - __half2float(h2)),
                            __float2half(v.w - __half2float(h3)));
}

// ---------------------------------------------------------------------------
// Transpose + convert: W[K][N] fp32 -> T[N][K] fp16 single
// ---------------------------------------------------------------------------
__global__ void wtcvt_kernel(const float* __restrict__ W,
                             __half* __restrict__ T, int K, int N)
{
    __shared__ float t[32][33];
    const int k0 = blockIdx.x * 32;
    const int n0 = blockIdx.y * 32;
    const int tx = threadIdx.x, ty = threadIdx.y;
    #pragma unroll
    for (int i = 0; i < 32; i += 8)
        t[ty + i][tx] = W[(size_t)(k0 + ty + i) * N + n0 + tx];
    __syncthreads();
    #pragma unroll
    for (int i = 0; i < 32; i += 8)
        T[(size_t)(n0 + ty + i) * K + k0 + tx] = __float2half(t[tx][ty + i]);
}

// ---------------------------------------------------------------------------
// K/V prep: K, V -> single fp16, per-head layout [h][tok][64].
// ---------------------------------------------------------------------------
__global__ void kvprep_kernel(const float* __restrict__ qkv,
                              __half* __restrict__ kf,
                              __half* __restrict__ vf)
{
    const int t = blockIdx.x;
    const int i = threadIdx.x;               // 0..191
    const int h = (4 * i) >> 6, d = (4 * i) & 63;
    const size_t o = ((size_t)h * SEQ + t) * HD + d;

    float4 kv = *(const float4*)&qkv[(size_t)t * QKV3 + 768 + 4 * i];
    *(__half2*)&kf[o]     = __half2(__float2half(kv.x), __float2half(kv.y));
    *(__half2*)&kf[o + 2] = __half2(__float2half(kv.z), __float2half(kv.w));

    float4 vv = *(const float4*)&qkv[(size_t)t * QKV3 + 1536 + 4 * i];
    *(__half2*)&vf[o]     = __half2(__float2half(vv.x), __float2half(vv.y));
    *(__half2*)&vf[o + 2] = __half2(__float2half(vv.z), __float2half(vv.w));
}

// ---------------------------------------------------------------------------
// fp16 2-term tensor-core GEMM: C = (Ah+Al)[M,K] * B[N,K]^T + bias
// Structure identical to the proven R11/R14 kernel minus the third term.
// Stage = 3 tiles (Ah, Al, B) = 30720B; 2 stages; 2 CTAs/SM.
// ---------------------------------------------------------------------------
#define GT_TILE  10240u   // 128 * 40 * 2 bytes
#define GT_STAGE 30720u   // 3 tiles (Ah,Al,B)

__global__ __launch_bounds__(256, 2)
void gemm_mma2_kernel(const __half* __restrict__ Ah,
                      const __half* __restrict__ Al,
                      const __half* __restrict__ B,
                      const float* __restrict__ bias,
                      float* __restrict__ C,
                      int M, int N, int K)
{
    extern __shared__ char gsm[];
    const uint32_t smB = (uint32_t)__cvta_generic_to_shared(gsm);

    const int tid  = threadIdx.x;
    const int warp = tid >> 5, lane = tid & 31;
    const int wm   = warp >> 2;
    const int wn   = warp & 3;
    const int m0   = blockIdx.y * 128;
    const int n0   = blockIdx.x * 128;

    float acc[4][4][4];
    #pragma unroll
    for (int a = 0; a < 4; a++)
        #pragma unroll
        for (int b = 0; b < 4; b++)
            #pragma unroll
            for (int c = 0; c < 4; c++) acc[a][b][c] = 0.0f;

    auto copyChunk = [&](int k0c, int buf) {
        const uint32_t sb = smB + (uint32_t)buf * GT_STAGE;
        #pragma unroll
        for (int t = 0; t < 3; t++) {
            const __half* gp = (t == 0) ? Ah : (t == 1) ? Al : B;
            const int base = (t < 2) ? m0 : n0;
            #pragma unroll
            for (int s = 0; s < 2; s++) {
                const int cid = tid + 256 * s;
                const int row = cid >> 2, kc = cid & 3;
                cp_async16(sb + t * GT_TILE + (uint32_t)(row * 40 + kc * 8) * 2,
                           gp + (size_t)(base + row) * K + k0c + kc * 8);
            }
        }
        cp_commit();
    };

    const int T = K >> 5;
    copyChunk(0, 0);

    for (int it = 0; it < T; it++) {
        cp_wait0();
        __syncthreads();
        if (it + 1 < T) copyChunk((it + 1) << 5, (it + 1) & 1);

        const uint32_t stg = smB + (uint32_t)(it & 1) * GT_STAGE;
        const int arow = wm * 64 + (lane & 15);
        const int brow = wn * 32 + (lane & 15);
        const int chi  = (lane >> 4) * 8;

        #pragma unroll
        for (int ks = 0; ks < 2; ks++) {
            const int col = ks * 16 + chi;
            uint32_t b2[2][4];
            #pragma unroll
            for (int nt = 0; nt < 2; nt++) {
                const uint32_t bd = stg + 2 * GT_TILE +
                                    (uint32_t)((brow + nt * 16) * 40 + col) * 2;
                LDSM_X4(b2[nt], bd);
            }
            #pragma unroll
            for (int mt = 0; mt < 4; mt++) {
                uint32_t a_h[4], a_l[4];
                const uint32_t ad = stg + (uint32_t)((arow + mt * 16) * 40 + col) * 2;
                LDSM_X4(a_h, ad);
                LDSM_X4(a_l, ad + GT_TILE);
                #pragma unroll
                for (int j = 0; j < 4; j++) {
                    const int nt = j >> 1, hf = j & 1;
                    mma16816h(acc[mt][j], a_h, b2[nt][hf], b2[nt][hf + 2]);
                    mma16816h(acc[mt][j], a_l, b2[nt][hf], b2[nt][hf + 2]);
                }
            }
        }
    }

    #pragma unroll
    for (int mt = 0; mt < 4; mt++) {
        const int r0 = m0 + wm * 64 + mt * 16 + (lane >> 2);
        #pragma unroll
        for (int j = 0; j < 4; j++) {
            const int cn = n0 + wn * 32 + j * 8 + 2 * (lane & 3);
            const float bx = bias[cn], by = bias[cn + 1];
            *(float2*)&C[(size_t)r0 * N + cn] =
                make_float2(acc[mt][j][0] + bx, acc[mt][j][1] + by);
            *(float2*)&C[(size_t)(r0 + 8) * N + cn] =
                make_float2(acc[mt][j][2] + bx, acc[mt][j][3] + by);
        }
    }
}

// ---------------------------------------------------------------------------
// Tensor-core strided flash attention, single-fp16 Q/K/P/V (unchanged R15).
// Block = 128 q x 1 head x 1 branch, 256 threads, 36.9KB smem, 2 CTAs/SM.
// ---------------------------------------------------------------------------
#define AP 72                       // smem pitch (fp16 elems)
#define A_V    18432u               // V ring base; K ring base = 0 (2 x 9216 each)
#define A_SMEM 36864u

__global__ __launch_bounds__(256, 2)
void attn_mma_kernel(const float* __restrict__ qkv,
                     const __half* __restrict__ kf,
                     const __half* __restrict__ vf,
                     float* __restrict__ attn_out)
{
    extern __shared__ char asm_[];
    const uint32_t smB = (uint32_t)__cvta_generic_to_shared(asm_);

    const int br = blockIdx.z;
    int L, dil;
    if (br == 0)      { L = 2048; dil = 1; }
    else if (br == 1) { L = 4096; dil = 2; }
    else              { L = 2048; dil = 4; }

    const int q0 = blockIdx.x * 128;
    if (q0 >= L) return;
    const int h    = blockIdx.y;
    const int tid  = threadIdx.x;
    const int warp = tid >> 5, lane = tid & 31;

    const size_t hoff = (size_t)h * SEQ * HD;

    auto copyKV = [&](int kt, int buf) {
        const int tok0 = kt * 64;
        const uint32_t kb = smB + (uint32_t)buf * 9216u;
        const uint32_t vb = smB + A_V + (uint32_t)buf * 9216u;
        #pragma unroll
        for (int i = 0; i < 4; i++) {
            const int flat = tid + 256 * i;          // 0..1023
            const int sel  = flat >> 9;              // 0:K 1:V
            const int r    = (flat >> 3) & 63;
            const int c    = flat & 7;
            const size_t src = hoff + (size_t)(tok0 + r) * dil * HD + c * 8;
            const uint32_t doff = (uint32_t)(r * AP + c * 8) * 2;
            cp_async16((sel ? vb : kb) + doff, (sel ? vf : kf) + src);
        }
        cp_commit();
    };

    const int nkt = L >> 6;

    // Prologue: stage Q (scaled, single fp16) into smem (region later
    // recycled for the K/V rings), read fragments, then start copies.
    {
        const int qr = tid >> 1, qc0 = (tid & 1) * 32;
        const float* qsrc = qkv + (size_t)(q0 + qr) * dil * QKV3 + h * 64 + qc0;
        __half* Qs = (__half*)asm_;
        #pragma unroll
        for (int i = 0; i < 8; i++) {
            float4 v = *(const float4*)&qsrc[4 * i];
            v.x *= QSCALE2; v.y *= QSCALE2; v.z *= QSCALE2; v.w *= QSCALE2;
            const int o = qr * AP + qc0 + 4 * i;
            *(__half2*)&Qs[o]     = __half2(__float2half(v.x), __float2half(v.y));
            *(__half2*)&Qs[o + 2] = __half2(__float2half(v.z), __float2half(v.w));
        }
    }
    __syncthreads();

    uint32_t qf[4][4];
    {
        const int qrow = 16 * warp + (lane & 15);
        #pragma unroll
        for (int ks = 0; ks < 4; ks++) {
            const uint32_t ad = smB + (uint32_t)(qrow * AP + ks * 16 + (lane >> 4) * 8) * 2;
            LDSM_X4(qf[ks], ad);
        }
    }
    __syncthreads();   // all warps done reading Q before K ring overwrites it

    copyKV(0, 0);

    float o[8][4];
    #pragma unroll
    for (int j = 0; j < 8; j++)
        #pragma unroll
        for (int c = 0; c < 4; c++) o[j][c] = 0.0f;
    float mrA = -1e30f, mrB = -1e30f, lrA = 0.0f, lrB = 0.0f;

    for (int kt = 0; kt < nkt; kt++) {
        cp_wait0();
        __syncthreads();
        if (kt + 1 < nkt) copyKV(kt + 1, (kt + 1) & 1);

        const int buf = kt & 1;
        const uint32_t kbase = smB + (uint32_t)buf * 9216u;
        const uint32_t vbase = smB + A_V + (uint32_t)buf * 9216u;

        // ---- S = Q K^T (single fp16) ----
        float s[8][4];
        #pragma unroll
        for (int j = 0; j < 8; j++)
            #pragma unroll
            for (int c = 0; c < 4; c++) s[j][c] = 0.0f;

        #pragma unroll
        for (int ks = 0; ks < 4; ks++) {
            uint32_t kfr[4][4];
            #pragma unroll
            for (int g = 0; g < 4; g++) {
                const uint32_t ad = kbase +
                    (uint32_t)((g * 16 + (lane & 15)) * AP + ks * 16 + (lane >> 4) * 8) * 2;
                LDSM_X4(kfr[g], ad);
            }
            #pragma unroll
            for (int g = 0; g < 4; g++) {
                mma16816h(s[2 * g],     qf[ks], kfr[g][0], kfr[g][2]);
                mma16816h(s[2 * g + 1], qf[ks], kfr[g][1], kfr[g][3]);
            }
        }

        // ---- online softmax in base-2 units; exp = single MUFU ex2 ----
        float mA = -1e30f, mB = -1e30f;
        #pragma unroll
        for (int j = 0; j < 8; j++) {
            mA = fmaxf(mA, fmaxf(s[j][0], s[j][1]));
            mB = fmaxf(mB, fmaxf(s[j][2], s[j][3]));
        }
        mA = fmaxf(mA, __shfl_xor_sync(0xffffffffu, mA, 1));
        mA = fmaxf(mA, __shfl_xor_sync(0xffffffffu, mA, 2));
        mB = fmaxf(mB, __shfl_xor_sync(0xffffffffu, mB, 1));
        mB = fmaxf(mB, __shfl_xor_sync(0xffffffffu, mB, 2));

        const float mnA = fmaxf(mrA, mA), mnB = fmaxf(mrB, mB);
        const float alA = ex2(mrA - mnA), alB = ex2(mrB - mnB);
        mrA = mnA; mrB = mnB;

        float lsA = 0.0f, lsB = 0.0f;
        #pragma unroll
        for (int j = 0; j < 8; j++) {
            s[j][0] = ex2(s[j][0] - mnA);
            s[j][1] = ex2(s[j][1] - mnA);
            s[j][2] = ex2(s[j][2] - mnB);
            s[j][3] = ex2(s[j][3] - mnB);
            lsA += s[j][0] + s[j][1];
            lsB += s[j][2] + s[j][3];
        }
        lsA += __shfl_xor_sync(0xffffffffu, lsA, 1);
        lsA += __shfl_xor_sync(0xffffffffu, lsA, 2);
        lsB += __shfl_xor_sync(0xffffffffu, lsB, 1);
        lsB += __shfl_xor_sync(0xffffffffu, lsB, 2);
        lrA = lrA * alA + lsA;
        lrB = lrB * alB + lsB;

        #pragma unroll
        for (int j = 0; j < 8; j++) {
            o[j][0] *= alA; o[j][1] *= alA;
            o[j][2] *= alB; o[j][3] *= alB;
        }

        // ---- O += P V  (P single fp16 from regs; V single in smem) ----
        #pragma unroll
        for (int t = 0; t < 4; t++) {
            uint32_t pa[4];
            pa[0] = cvt2_f16(s[2 * t][0],     s[2 * t][1]);
            pa[1] = cvt2_f16(s[2 * t][2],     s[2 * t][3]);
            pa[2] = cvt2_f16(s[2 * t + 1][0], s[2 * t + 1][1]);
            pa[3] = cvt2_f16(s[2 * t + 1][2], s[2 * t + 1][3]);
            #pragma unroll
            for (int g = 0; g < 4; g++) {
                uint32_t vf4[4];
                const uint32_t ad = vbase +
                    (uint32_t)((16 * t + ((lane >> 3) & 1) * 8 + (lane & 7)) * AP +
                               16 * g + (lane >> 4) * 8) * 2;
                LDSM_X4_T(vf4, ad);
                mma16816h(o[2 * g],     pa, vf4[0], vf4[1]);
                mma16816h(o[2 * g + 1], pa, vf4[2], vf4[3]);
            }
        }
    }

    // Epilogue: o/l * (1/3), scatter-add
    const float w3 = 1.0f / 3.0f;
    const float invA = w3 / lrA, invB = w3 / lrB;
    const int rA = q0 + 16 * warp + (lane >> 2);
    float* baseA = attn_out + (size_t)rA * dil * EMB + h * 64;
    float* baseB = attn_out + (size_t)(rA + 8) * dil * EMB + h * 64;
    #pragma unroll
    for (int j = 0; j < 8; j++) {
        const int c = 8 * j + 2 * (lane & 3);
        atomicAdd(baseA + c,     o[j][0] * invA);
        atomicAdd(baseA + c + 1, o[j][1] * invA);
        atomicAdd(baseB + c,     o[j][2] * invB);
        atomicAdd(baseB + c + 1, o[j][3] * invB);
    }
}

// ---------------------------------------------------------------------------
// Launch
// ---------------------------------------------------------------------------
extern "C" void kernel_launch(void* const* d_in, const int* in_sizes, int n_in,
                              void* d_out, int out_size)
{
    const float* x    = (const float*)d_in[0];
    const float* Wqkv = (const float*)d_in[1];
    const float* bqkv = (const float*)d_in[2];
    const float* Wout = (const float*)d_in[3];
    const float* bout = (const float*)d_in[4];
    float*       out  = (float*)d_out;

    float *qkvp, *attnp;
    __half *xh, *xl, *ah, *al, *wq, *wo, *kfp, *vfp;
    cudaGetSymbolAddress((void**)&qkvp,  g_qkv);
    cudaGetSymbolAddress((void**)&attnp, g_attn);
    cudaGetSymbolAddress((void**)&xh, g_xh);  cudaGetSymbolAddress((void**)&xl, g_xl);
    cudaGetSymbolAddress((void**)&ah, g_ah);  cudaGetSymbolAddress((void**)&al, g_al);
    cudaGetSymbolAddress((void**)&wq, g_wq);  cudaGetSymbolAddress((void**)&wo, g_wo);
    cudaGetSymbolAddress((void**)&kfp, g_kf); cudaGetSymbolAddress((void**)&vfp, g_vf);

    const int GEMM_SMEM = 2 * GT_STAGE;   // 61440
    (void)cudaFuncSetAttribute((const void*)gemm_mma2_kernel,
                               cudaFuncAttributeMaxDynamicSharedMemorySize, GEMM_SMEM);
    (void)cudaFuncSetAttribute((const void*)attn_mma_kernel,
                               cudaFuncAttributeMaxDynamicSharedMemorySize, A_SMEM);

    // 1) Prep: split x to fp16 hi/lo; weights -> fp16 transposed single
    splitf16_kernel<<<(SEQ * EMB / 4 + 255) / 256, 256>>>(x, xh, xl, SEQ * EMB / 4);
    wtcvt_kernel<<<dim3(EMB / 32, QKV3 / 32), dim3(32, 8)>>>(Wqkv, wq, EMB, QKV3);
    wtcvt_kernel<<<dim3(EMB / 32, EMB / 32),  dim3(32, 8)>>>(Wout, wo, EMB, EMB);

    // 2) QKV GEMM (fp16 2-term)
    {
        dim3 grid(QKV3 / 128, SEQ / 128);
        gemm_mma2_kernel<<<grid, 256, GEMM_SMEM>>>(xh, xl, wq, bqkv, qkvp,
                                                   SEQ, QKV3, EMB);
    }

    // 3) K/V prep to fp16
    kvprep_kernel<<<SEQ, 192>>>(qkvp, kfp, vfp);

    // 4) Zero attention accumulator
    cudaMemsetAsync(attnp, 0, (size_t)SEQ * EMB * sizeof(float));

    // 5) Attention (tensor cores, all 3 branches)
    {
        dim3 grid(32, NH, 3);
        attn_mma_kernel<<<grid, 256, A_SMEM>>>(qkvp, kfp, vfp, attnp);
    }

    // 6) Split attention output to fp16, then output projection (fp16 2-term)
    splitf16_kernel<<<(SEQ * EMB / 4 + 255) / 256, 256>>>(attnp, ah, al, SEQ * EMB / 4);
    {
        dim3 grid(EMB / 128, SEQ / 128);
        gemm_mma2_kernel<<<grid, 256, GEMM_SMEM>>>(ah, al, wo, bout, out,
                                                   SEQ, EMB, EMB);
    }
}